// round 9
// baseline (speedup 1.0000x reference)
#include <cuda_runtime.h>
#include <cuda_bf16.h>
#include <cstdint>

// ---------------------------------------------------------------------------
// Problem constants
// ---------------------------------------------------------------------------
#define N_NODES 100000
#define N_EDGES 1600000
#define D_NODE  128
#define D_EDGE  128
#define D_IN    256
#define HID     256
#define D_OUT   128

// ---------------------------------------------------------------------------
// Scratch (device globals; allocations are forbidden)
// ---------------------------------------------------------------------------
__device__ __align__(16) float g_sum[(size_t)N_NODES * D_EDGE];
__device__ int g_cnt[N_NODES];

// Weight blob in EXACT mma.sync A-fragment order, bf16 hi/lo terms:
//   b32 index = layerBase + ((kstep*NFT + ft)*2 + term)*128 + lane*4 + reg
#define WF_L2_B32 65536
#define WF_L3_B32 131072
#define WF_TOTAL_B32 163840
__device__ __align__(16) uint4 g_wfrag[WF_TOTAL_B32 / 4];

// ---------------------------------------------------------------------------
// SMEM map: activations only (hi + lo), [256 feat][72 bf16] stride 144 B.
// L3 f32 transpose scratch (128 x 68 f32, stride 272 B) overlays act area.
// ---------------------------------------------------------------------------
#define ACT_HI_OFF 0
#define ACT_LO_OFF 36864
#define SMEM_BYTES 73728

// ---------------------------------------------------------------------------
// PTX helpers (arch-portable, valid at compute_103)
// ---------------------------------------------------------------------------
__device__ __forceinline__ uint32_t smem_to_u32(const void* p) {
    uint32_t a;
    asm("{ .reg .u64 t; cvta.to.shared.u64 t, %1; cvt.u32.u64 %0, t; }"
        : "=r"(a) : "l"(p));
    return a;
}

#define LDMX4T(r, addr) \
    asm volatile("ldmatrix.sync.aligned.m8n8.x4.trans.shared.b16 {%0,%1,%2,%3}, [%4];" \
        : "=r"((r)[0]), "=r"((r)[1]), "=r"((r)[2]), "=r"((r)[3]) : "r"(addr))

#define MMA_BF16(d, a, b0v, b1v) \
    asm volatile("mma.sync.aligned.m16n8k16.row.col.f32.bf16.bf16.f32 " \
        "{%0,%1,%2,%3},{%4,%5,%6,%7},{%8,%9},{%0,%1,%2,%3};" \
        : "+f"((d)[0]), "+f"((d)[1]), "+f"((d)[2]), "+f"((d)[3]) \
        : "r"((a)[0]), "r"((a)[1]), "r"((a)[2]), "r"((a)[3]), \
          "r"(b0v), "r"(b1v))

// fp32 pair -> packed bf16x2 hi + lo (a in low half)
__device__ __forceinline__ void split_pack(float a, float b,
                                           uint32_t& hi, uint32_t& lo) {
    __nv_bfloat16 ah = __float2bfloat16(a);
    __nv_bfloat16 bh = __float2bfloat16(b);
    __nv_bfloat16 al = __float2bfloat16(a - __bfloat162float(ah));
    __nv_bfloat16 bl = __float2bfloat16(b - __bfloat162float(bh));
    hi = ((uint32_t)__bfloat16_as_ushort(bh) << 16) | (uint32_t)__bfloat16_as_ushort(ah);
    lo = ((uint32_t)__bfloat16_as_ushort(bl) << 16) | (uint32_t)__bfloat16_as_ushort(al);
}

// ---------------------------------------------------------------------------
// Kernel 1: zero scratch
// ---------------------------------------------------------------------------
__global__ void zero_kernel() {
    int i = blockIdx.x * blockDim.x + threadIdx.x;
    const int total = N_NODES * D_EDGE;
    if (i < total) g_sum[i] = 0.0f;
    if (i < N_NODES) g_cnt[i] = 0;
}

// ---------------------------------------------------------------------------
// Kernel 2: weight prep — bf16 hi/lo fragments in mma A-operand order
// ---------------------------------------------------------------------------
__global__ void prep_kernel(const float* __restrict__ W1,
                            const float* __restrict__ W2,
                            const float* __restrict__ W3) {
    int i = blockIdx.x * blockDim.x + threadIdx.x;
    if (i >= WF_TOTAL_B32) return;
    uint32_t* blob = (uint32_t*)g_wfrag;
    const float* W; int idx, Nl, NFT;
    if (i < WF_L2_B32)      { W = W1; idx = i;             Nl = 256; NFT = 16; }
    else if (i < WF_L3_B32) { W = W2; idx = i - WF_L2_B32; Nl = 256; NFT = 16; }
    else                    { W = W3; idx = i - WF_L3_B32; Nl = 128; NFT = 8;  }
    int reg   = idx & 3;
    int lane  = (idx >> 2) & 31;
    int term  = (idx >> 7) & 1;
    int ft    = (idx >> 8) % NFT;
    int kstep = (idx >> 8) / NFT;
    int r = lane >> 2, t = lane & 3;
    int m = ft * 16 + r + (reg & 1) * 8;
    int k = kstep * 16 + t * 2 + (reg >> 1) * 8;
    float w0 = __ldg(W + (size_t)k * Nl + m);
    float w1 = __ldg(W + (size_t)(k + 1) * Nl + m);
    uint32_t hi, lo;
    split_pack(w0, w1, hi, lo);
    blob[i] = term ? lo : hi;
}

// ---------------------------------------------------------------------------
// Kernel 3: scatter-add (red.v4, streaming reads) + degree count.
// ---------------------------------------------------------------------------
__global__ void __launch_bounds__(256)
scatter_kernel(const int* __restrict__ col,
               const float4* __restrict__ edge_attr,
               int n_edges) {
    long long gid = (long long)blockIdx.x * blockDim.x + threadIdx.x;
    if (gid >= (long long)n_edges * 32) return;
    int e = (int)(gid >> 5);
    int c = (int)(gid & 31);
    int dst = __ldg(col + e);
    if (c == 0) atomicAdd(&g_cnt[dst], 1);
    float4 v = __ldg(edge_attr + (size_t)e * 32 + c);
    float* p = g_sum + (size_t)dst * D_EDGE + c * 4;
    asm volatile("red.global.add.v4.f32 [%0], {%1,%2,%3,%4};"
                 :: "l"(p), "f"(v.x), "f"(v.y), "f"(v.z), "f"(v.w)
                 : "memory");
}

// ---------------------------------------------------------------------------
// Layer MMA: warp owns NT 16-feat tiles x 32 nodes (m-half mh).
// B fragments amortized over NT A tiles -> half the ldmatrix traffic.
// ---------------------------------------------------------------------------
template<int NT>
__device__ __forceinline__ void layer_mma(
    float (*acc)[4][4],              // [NT][node-group 0..3][4]
    const uint4* __restrict__ wf,    // layer base (uint4 units)
    int ftBase, int NFT, int mh,
    uint32_t actHi, uint32_t actLo, int lane)
{
    const uint32_t bK  = (uint32_t)(lane & 15);
    const uint32_t bMH = (uint32_t)((lane >> 4) * 8);
    #pragma unroll
    for (int kstep = 0; kstep < 16; kstep++) {
        uint32_t ah[NT][4], al[NT][4];
        #pragma unroll
        for (int i = 0; i < NT; i++) {
            const uint4* p = wf + (size_t)((kstep * NFT + ftBase + i) * 2) * 32 + lane;
            uint4 h = __ldg(p);
            uint4 l = __ldg(p + 32);
            ah[i][0] = h.x; ah[i][1] = h.y; ah[i][2] = h.z; ah[i][3] = h.w;
            al[i][0] = l.x; al[i][1] = l.y; al[i][2] = l.z; al[i][3] = l.w;
        }
        const uint32_t kByte = (uint32_t)(kstep * 16 + (int)bK) * 144u;
        #pragma unroll
        for (int mtl = 0; mtl < 2; mtl++) {
            const uint32_t mByte = (uint32_t)((mh * 2 + mtl) * 16 + (int)bMH) * 2u;
            uint32_t bh[4], bl[4];
            LDMX4T(bh, actHi + kByte + mByte);
            LDMX4T(bl, actLo + kByte + mByte);
            #pragma unroll
            for (int i = 0; i < NT; i++) {
                #pragma unroll
                for (int h = 0; h < 2; h++) {
                    MMA_BF16(acc[i][mtl * 2 + h], ah[i], bh[2 * h], bh[2 * h + 1]);
                    MMA_BF16(acc[i][mtl * 2 + h], ah[i], bl[2 * h], bl[2 * h + 1]);
                    MMA_BF16(acc[i][mtl * 2 + h], al[i], bh[2 * h], bh[2 * h + 1]);
                }
            }
        }
    }
}

// ---------------------------------------------------------------------------
// Kernel 4: fused 3-layer MLP. CTA = 64 nodes, 256 threads, 2 CTAs/SM.
// Warp (fg, mh): fg = warp&3 -> 64-feature group, mh = warp>>2 -> 32-node half.
// ---------------------------------------------------------------------------
__global__ void __launch_bounds__(256, 2)
mlp_kernel(const float* __restrict__ x,
           const float* __restrict__ b1,
           const float* __restrict__ b2,
           const float* __restrict__ b3,
           float* __restrict__ out, int n)
{
    extern __shared__ char sm[];
    const uint32_t sb    = smem_to_u32(sm);
    const uint32_t actHi = sb + ACT_HI_OFF;
    const uint32_t actLo = sb + ACT_LO_OFF;

    const int tid  = threadIdx.x;
    const int warp = tid >> 5;
    const int lane = tid & 31;
    const int g    = lane >> 2;
    const int t    = lane & 3;
    const int fg   = warp & 3;     // feature group
    const int mh   = warp >> 2;    // node half (0: nodes 0-31, 1: 32-63)
    const int m0   = blockIdx.x * 64;

    // ---- input fill: act[feat][node] = split(concat(x, mean)) --------------
    {
        int r = tid >> 2;           // local node 0..63
        int q = tid & 3;            // feature quarter
        int m = m0 + r;
        bool valid = (m < n);
        float inv = 1.0f;
        if (valid) inv = 1.0f / fmaxf((float)__ldg(&g_cnt[m]), 1.0f);
        const float4* xr = (const float4*)(x + (size_t)(valid ? m : 0) * D_NODE);
        const float4* gr = (const float4*)(g_sum + (size_t)(valid ? m : 0) * D_EDGE);
        #pragma unroll
        for (int j = 0; j < 16; j++) {
            int fb = q * 64 + j * 4;
            float4 v = make_float4(0.f, 0.f, 0.f, 0.f);
            if (valid) {
                if (q < 2) v = __ldg(xr + q * 16 + j);
                else {
                    v = __ldg(gr + (q - 2) * 16 + j);
                    v.x *= inv; v.y *= inv; v.z *= inv; v.w *= inv;
                }
            }
            float vals[4] = {v.x, v.y, v.z, v.w};
            #pragma unroll
            for (int e = 0; e < 4; e++) {
                __nv_bfloat16 hi = __float2bfloat16(vals[e]);
                __nv_bfloat16 lo = __float2bfloat16(vals[e] - __bfloat162float(hi));
                size_t o = (size_t)(fb + e) * 144 + (size_t)r * 2;
                *(__nv_bfloat16*)(sm + ACT_HI_OFF + o) = hi;
                *(__nv_bfloat16*)(sm + ACT_LO_OFF + o) = lo;
            }
        }
    }
    __syncthreads();

    float acc[4][4][4];

    // ---- Layers 1 & 2 (K=256, N=256): warp = 64 feats x 32 nodes -----------
    #pragma unroll 1
    for (int L = 0; L < 2; L++) {
        const uint4* wf = g_wfrag + (L == 0 ? 0 : WF_L2_B32 / 4);
        #pragma unroll
        for (int i = 0; i < 4; i++)
            #pragma unroll
            for (int ng = 0; ng < 4; ng++)
                #pragma unroll
                for (int q = 0; q < 4; q++) acc[i][ng][q] = 0.f;

        layer_mma<4>(acc, wf, fg * 4, 16, mh, actHi, actLo, lane);

        __syncthreads();     // all warps done READING act for this layer

        const float* bias = (L == 0) ? b1 : b2;
        #pragma unroll
        for (int i = 0; i < 4; i++) {
            int fb = fg * 64 + i * 16;
            float bg  = __ldg(bias + fb + g);
            float bg8 = __ldg(bias + fb + g + 8);
            size_t rowG  = (size_t)(fb + g) * 144;
            size_t rowG8 = (size_t)(fb + g + 8) * 144;
            #pragma unroll
            for (int ng = 0; ng < 4; ng++) {
                float v0 = fmaxf(acc[i][ng][0] + bg,  0.f);
                float v1 = fmaxf(acc[i][ng][1] + bg,  0.f);
                float v2 = fmaxf(acc[i][ng][2] + bg8, 0.f);
                float v3 = fmaxf(acc[i][ng][3] + bg8, 0.f);
                uint32_t h01, l01, h23, l23;
                split_pack(v0, v1, h01, l01);
                split_pack(v2, v3, h23, l23);
                size_t mB = (size_t)(mh * 32 + ng * 8 + 2 * t) * 2;
                *(uint32_t*)(sm + ACT_HI_OFF + rowG  + mB) = h01;
                *(uint32_t*)(sm + ACT_LO_OFF + rowG  + mB) = l01;
                *(uint32_t*)(sm + ACT_HI_OFF + rowG8 + mB) = h23;
                *(uint32_t*)(sm + ACT_LO_OFF + rowG8 + mB) = l23;
            }
        }
        __syncthreads();     // writes visible before next layer reads
    }

    // ---- Layer 3 (K=256, N=128): warp = 32 feats x 32 nodes -----------------
    #pragma unroll
    for (int i = 0; i < 2; i++)
        #pragma unroll
        for (int ng = 0; ng < 4; ng++)
            #pragma unroll
            for (int q = 0; q < 4; q++) acc[i][ng][q] = 0.f;

    layer_mma<2>(acc, g_wfrag + WF_L3_B32 / 4, fg * 2, 8, mh,
                 actHi, actLo, lane);

    // ---- final epilogue: bias, transpose via f32 scratch, coalesced store ---
    {
        __syncthreads();     // all done reading act (scratch overlays it)
        #pragma unroll
        for (int i = 0; i < 2; i++) {
            int fb = fg * 32 + i * 16;
            float bg  = __ldg(b3 + fb + g);
            float bg8 = __ldg(b3 + fb + g + 8);
            #pragma unroll
            for (int ng = 0; ng < 4; ng++) {
                float2 v01 = make_float2(acc[i][ng][0] + bg,  acc[i][ng][1] + bg);
                float2 v23 = make_float2(acc[i][ng][2] + bg8, acc[i][ng][3] + bg8);
                size_t mB = (size_t)(mh * 32 + ng * 8 + 2 * t) * 4;
                *(float2*)(sm + (size_t)(fb + g)     * 272 + mB) = v01;
                *(float2*)(sm + (size_t)(fb + g + 8) * 272 + mB) = v23;
            }
        }
        __syncthreads();
        int mloc = tid >> 2, fgrp = tid & 3;
        int m = m0 + mloc;
        if (m < n) {
            const float* scr = (const float*)sm;
            #pragma unroll
            for (int i = 0; i < 8; i++) {
                int f = fgrp * 32 + i * 4;
                float4 v;
                v.x = scr[(f + 0) * 68 + mloc];
                v.y = scr[(f + 1) * 68 + mloc];
                v.z = scr[(f + 2) * 68 + mloc];
                v.w = scr[(f + 3) * 68 + mloc];
                *(float4*)(out + (size_t)m * D_OUT + f) = v;
            }
        }
    }
}

// ---------------------------------------------------------------------------
// kernel_launch
// Inputs: 0=x [N,128] f32, 1=edge_index [2,E] i32, 2=edge_attr [E,128] f32,
//         3=W1 [256,256], 4=b1, 5=W2 [256,256], 6=b2, 7=W3 [256,128], 8=b3.
// ---------------------------------------------------------------------------
extern "C" void kernel_launch(void* const* d_in, const int* in_sizes, int n_in,
                              void* d_out, int out_size) {
    const float* x  = (const float*)d_in[0];
    const int* ei   = (const int*)d_in[1];
    const float* ea = (const float*)d_in[2];
    const float* W1 = (const float*)d_in[3];
    const float* b1 = (const float*)d_in[4];
    const float* W2 = (const float*)d_in[5];
    const float* b2 = (const float*)d_in[6];
    const float* W3 = (const float*)d_in[7];
    const float* b3 = (const float*)d_in[8];
    float* out = (float*)d_out;

    const int n = in_sizes[0] / D_NODE;              // 100000
    const int n_edges = in_sizes[2] / D_EDGE;        // 1600000
    const int* col = ei + n_edges;                   // edge_index[1]

    // 1) zero scratch
    {
        int total = N_NODES * D_EDGE;
        zero_kernel<<<(total + 255) / 256, 256>>>();
    }
    // 2) weight prep (fragment-order split)
    prep_kernel<<<(WF_TOTAL_B32 + 255) / 256, 256>>>(W1, W2, W3);
    // 3) scatter-add + counts (streaming reads, red.v4 atomics)
    {
        long long threads = (long long)n_edges * 32;
        int blocks = (int)((threads + 255) / 256);
        scatter_kernel<<<blocks, 256>>>(col, (const float4*)ea, n_edges);
    }
    // 4) fused tensor-core MLP
    {
        static int smem_set = 0;
        if (!smem_set) {
            cudaFuncSetAttribute(mlp_kernel,
                                 cudaFuncAttributeMaxDynamicSharedMemorySize,
                                 SMEM_BYTES);
            smem_set = 1;
        }
        int blocks = (n + 63) / 64;                  // 1563
        mlp_kernel<<<blocks, 256, SMEM_BYTES>>>(x, b1, b2, b3, out, n);
    }
}

// round 10
// speedup vs baseline: 1.0687x; 1.0687x over previous
#include <cuda_runtime.h>
#include <cuda_bf16.h>
#include <cstdint>

// ---------------------------------------------------------------------------
// Problem constants
// ---------------------------------------------------------------------------
#define N_NODES 100000
#define N_EDGES 1600000
#define D_NODE  128
#define D_EDGE  128
#define D_IN    256
#define HID     256
#define D_OUT   128

// ---------------------------------------------------------------------------
// Scratch (device globals; allocations are forbidden)
// ---------------------------------------------------------------------------
__device__ __align__(16) float g_sum[(size_t)N_NODES * D_EDGE];
__device__ int g_cnt[N_NODES];

// Weight blob in EXACT mma.sync A-fragment order, bf16 hi/lo terms:
//   b32 index = layerBase + ((kstep*NFT + ft)*2 + term)*128 + lane*4 + reg
#define WF_L2_B32 65536
#define WF_L3_B32 131072
#define WF_TOTAL_B32 163840
__device__ __align__(16) uint4 g_wfrag[WF_TOTAL_B32 / 4];

// ---------------------------------------------------------------------------
// SMEM map: activations only (hi + lo), [256 feat][72 bf16] stride 144 B.
// L3 f32 transpose scratch (128 x 68 f32, stride 272 B) overlays act area.
// ---------------------------------------------------------------------------
#define ACT_HI_OFF 0
#define ACT_LO_OFF 36864
#define SMEM_BYTES 73728

// ---------------------------------------------------------------------------
// PTX helpers (arch-portable, valid at compute_103)
// ---------------------------------------------------------------------------
__device__ __forceinline__ uint32_t smem_to_u32(const void* p) {
    uint32_t a;
    asm("{ .reg .u64 t; cvta.to.shared.u64 t, %1; cvt.u32.u64 %0, t; }"
        : "=r"(a) : "l"(p));
    return a;
}

#define LDMX4T(r, addr) \
    asm volatile("ldmatrix.sync.aligned.m8n8.x4.trans.shared.b16 {%0,%1,%2,%3}, [%4];" \
        : "=r"((r)[0]), "=r"((r)[1]), "=r"((r)[2]), "=r"((r)[3]) : "r"(addr))

#define MMA_BF16(d, a, b0v, b1v) \
    asm volatile("mma.sync.aligned.m16n8k16.row.col.f32.bf16.bf16.f32 " \
        "{%0,%1,%2,%3},{%4,%5,%6,%7},{%8,%9},{%0,%1,%2,%3};" \
        : "+f"((d)[0]), "+f"((d)[1]), "+f"((d)[2]), "+f"((d)[3]) \
        : "r"((a)[0]), "r"((a)[1]), "r"((a)[2]), "r"((a)[3]), \
          "r"(b0v), "r"(b1v))

// fp32 pair -> packed bf16x2 hi + lo (a in low half, b in high half).
// Vectorized: one cvt.rn.bf16x2.f32 converts both values; bf16->f32
// reconstruction is a pure bit shift/mask (bf16 = top 16 bits of f32).
__device__ __forceinline__ void split_pack(float a, float b,
                                           uint32_t& hi, uint32_t& lo) {
    asm("cvt.rn.bf16x2.f32 %0, %1, %2;" : "=r"(hi) : "f"(b), "f"(a));
    float ah = __uint_as_float(hi << 16);
    float bh = __uint_as_float(hi & 0xffff0000u);
    float al = a - ah;
    float bl = b - bh;
    asm("cvt.rn.bf16x2.f32 %0, %1, %2;" : "=r"(lo) : "f"(bl), "f"(al));
}

// ---------------------------------------------------------------------------
// Kernel 1: zero scratch (float4 stores)
// ---------------------------------------------------------------------------
__global__ void zero_kernel() {
    int i = blockIdx.x * blockDim.x + threadIdx.x;
    const int total4 = N_NODES * D_EDGE / 4;
    if (i < total4)
        ((float4*)g_sum)[i] = make_float4(0.f, 0.f, 0.f, 0.f);
    if (i < N_NODES) g_cnt[i] = 0;
}

// ---------------------------------------------------------------------------
// Kernel 2: weight prep — bf16 hi/lo fragments in mma A-operand order
// ---------------------------------------------------------------------------
__global__ void prep_kernel(const float* __restrict__ W1,
                            const float* __restrict__ W2,
                            const float* __restrict__ W3) {
    int i = blockIdx.x * blockDim.x + threadIdx.x;
    if (i >= WF_TOTAL_B32) return;
    uint32_t* blob = (uint32_t*)g_wfrag;
    const float* W; int idx, Nl, NFT;
    if (i < WF_L2_B32)      { W = W1; idx = i;             Nl = 256; NFT = 16; }
    else if (i < WF_L3_B32) { W = W2; idx = i - WF_L2_B32; Nl = 256; NFT = 16; }
    else                    { W = W3; idx = i - WF_L3_B32; Nl = 128; NFT = 8;  }
    int reg   = idx & 3;
    int lane  = (idx >> 2) & 31;
    int term  = (idx >> 7) & 1;
    int ft    = (idx >> 8) % NFT;
    int kstep = (idx >> 8) / NFT;
    int r = lane >> 2, t = lane & 3;
    int m = ft * 16 + r + (reg & 1) * 8;
    int k = kstep * 16 + t * 2 + (reg >> 1) * 8;
    float w0 = __ldg(W + (size_t)k * Nl + m);
    float w1 = __ldg(W + (size_t)(k + 1) * Nl + m);
    uint32_t hi, lo;
    split_pack(w0, w1, hi, lo);
    blob[i] = term ? lo : hi;
}

// ---------------------------------------------------------------------------
// Kernel 3: scatter-add (red.v4, streaming reads) + degree count.
// ---------------------------------------------------------------------------
__global__ void __launch_bounds__(256)
scatter_kernel(const int* __restrict__ col,
               const float4* __restrict__ edge_attr,
               int n_edges) {
    long long gid = (long long)blockIdx.x * blockDim.x + threadIdx.x;
    if (gid >= (long long)n_edges * 32) return;
    int e = (int)(gid >> 5);
    int c = (int)(gid & 31);
    int dst = __ldg(col + e);
    if (c == 0) atomicAdd(&g_cnt[dst], 1);
    float4 v = __ldg(edge_attr + (size_t)e * 32 + c);
    float* p = g_sum + (size_t)dst * D_EDGE + c * 4;
    asm volatile("red.global.add.v4.f32 [%0], {%1,%2,%3,%4};"
                 :: "l"(p), "f"(v.x), "f"(v.y), "f"(v.z), "f"(v.w)
                 : "memory");
}

// ---------------------------------------------------------------------------
// Layer MMA (round-8 tiling: warp = NT*16 feats x 64 nodes), 3-term bf16.
// ---------------------------------------------------------------------------
template<int NT>
__device__ __forceinline__ void layer_mma(
    float acc[2][8][4],
    const uint4* __restrict__ wf,    // layer base (uint4 units)
    int ftBase, int NFT,
    uint32_t actHi, uint32_t actLo, int lane)
{
    const uint32_t bK  = (uint32_t)(lane & 15);
    const uint32_t bMH = (uint32_t)((lane >> 4) * 8);
    #pragma unroll
    for (int kstep = 0; kstep < 16; kstep++) {
        uint32_t ah[NT][4], al[NT][4];
        #pragma unroll
        for (int i = 0; i < NT; i++) {
            const uint4* p = wf + (size_t)((kstep * NFT + ftBase + i) * 2) * 32 + lane;
            uint4 h = __ldg(p);
            uint4 l = __ldg(p + 32);
            ah[i][0] = h.x; ah[i][1] = h.y; ah[i][2] = h.z; ah[i][3] = h.w;
            al[i][0] = l.x; al[i][1] = l.y; al[i][2] = l.z; al[i][3] = l.w;
        }
        const uint32_t kByte = (uint32_t)(kstep * 16 + (int)bK) * 144u;
        #pragma unroll
        for (int mt = 0; mt < 4; mt++) {
            const uint32_t mByte = (uint32_t)(mt * 16 + (int)bMH) * 2u;
            uint32_t bh[4], bl[4];
            LDMX4T(bh, actHi + kByte + mByte);
            LDMX4T(bl, actLo + kByte + mByte);
            #pragma unroll
            for (int i = 0; i < NT; i++) {
                #pragma unroll
                for (int h = 0; h < 2; h++) {
                    MMA_BF16(acc[i][mt * 2 + h], ah[i], bh[2 * h], bh[2 * h + 1]);
                    MMA_BF16(acc[i][mt * 2 + h], ah[i], bl[2 * h], bl[2 * h + 1]);
                    MMA_BF16(acc[i][mt * 2 + h], al[i], bh[2 * h], bh[2 * h + 1]);
                }
            }
        }
    }
}

// ---------------------------------------------------------------------------
// Kernel 4: fused 3-layer MLP. CTA = 64 nodes, 256 threads, 2 CTAs/SM.
// ---------------------------------------------------------------------------
__global__ void __launch_bounds__(256, 2)
mlp_kernel(const float* __restrict__ x,
           const float* __restrict__ b1,
           const float* __restrict__ b2,
           const float* __restrict__ b3,
           float* __restrict__ out, int n)
{
    extern __shared__ char sm[];
    const uint32_t sb    = smem_to_u32(sm);
    const uint32_t actHi = sb + ACT_HI_OFF;
    const uint32_t actLo = sb + ACT_LO_OFF;

    const int tid  = threadIdx.x;
    const int warp = tid >> 5;
    const int lane = tid & 31;
    const int g    = lane >> 2;
    const int t    = lane & 3;
    const int m0   = blockIdx.x * 64;

    // ---- input fill: act[feat][node] = split(concat(x, mean)) --------------
    {
        int r = tid >> 2;           // local node 0..63
        int q = tid & 3;            // feature quarter
        int m = m0 + r;
        bool valid = (m < n);
        float inv = 1.0f;
        if (valid) inv = 1.0f / fmaxf((float)__ldg(&g_cnt[m]), 1.0f);
        const float4* xr = (const float4*)(x + (size_t)(valid ? m : 0) * D_NODE);
        const float4* gr = (const float4*)(g_sum + (size_t)(valid ? m : 0) * D_EDGE);
        #pragma unroll
        for (int j = 0; j < 16; j++) {
            int fb = q * 64 + j * 4;
            float4 v = make_float4(0.f, 0.f, 0.f, 0.f);
            if (valid) {
                if (q < 2) v = __ldg(xr + q * 16 + j);
                else {
                    v = __ldg(gr + (q - 2) * 16 + j);
                    v.x *= inv; v.y *= inv; v.z *= inv; v.w *= inv;
                }
            }
            // vectorized split: 2 values per cvt; store 16-bit halves
            uint32_t h01, l01, h23, l23;
            split_pack(v.x, v.y, h01, l01);
            split_pack(v.z, v.w, h23, l23);
            size_t o0 = (size_t)(fb + 0) * 144 + (size_t)r * 2;
            size_t o1 = (size_t)(fb + 1) * 144 + (size_t)r * 2;
            size_t o2 = (size_t)(fb + 2) * 144 + (size_t)r * 2;
            size_t o3 = (size_t)(fb + 3) * 144 + (size_t)r * 2;
            *(uint16_t*)(sm + ACT_HI_OFF + o0) = (uint16_t)h01;
            *(uint16_t*)(sm + ACT_HI_OFF + o1) = (uint16_t)(h01 >> 16);
            *(uint16_t*)(sm + ACT_HI_OFF + o2) = (uint16_t)h23;
            *(uint16_t*)(sm + ACT_HI_OFF + o3) = (uint16_t)(h23 >> 16);
            *(uint16_t*)(sm + ACT_LO_OFF + o0) = (uint16_t)l01;
            *(uint16_t*)(sm + ACT_LO_OFF + o1) = (uint16_t)(l01 >> 16);
            *(uint16_t*)(sm + ACT_LO_OFF + o2) = (uint16_t)l23;
            *(uint16_t*)(sm + ACT_LO_OFF + o3) = (uint16_t)(l23 >> 16);
        }
    }
    __syncthreads();

    float acc[2][8][4];

    // ---- Layers 1 & 2 (K=256, N=256) ---------------------------------------
    #pragma unroll 1
    for (int L = 0; L < 2; L++) {
        const uint4* wf = g_wfrag + (L == 0 ? 0 : WF_L2_B32 / 4);
        #pragma unroll
        for (int i = 0; i < 2; i++)
            #pragma unroll
            for (int mt = 0; mt < 8; mt++)
                #pragma unroll
                for (int q = 0; q < 4; q++) acc[i][mt][q] = 0.f;

        layer_mma<2>(acc, wf, warp * 2, 16, actHi, actLo, lane);

        __syncthreads();     // all warps done READING act for this layer

        const float* bias = (L == 0) ? b1 : b2;
        const int nb = warp * 32;
        #pragma unroll
        for (int i = 0; i < 2; i++) {
            int fb = nb + i * 16;
            float bg  = __ldg(bias + fb + g);
            float bg8 = __ldg(bias + fb + g + 8);
            size_t rowG  = (size_t)(fb + g) * 144;
            size_t rowG8 = (size_t)(fb + g + 8) * 144;
            #pragma unroll
            for (int mt = 0; mt < 8; mt++) {
                float v0 = fmaxf(acc[i][mt][0] + bg,  0.f);
                float v1 = fmaxf(acc[i][mt][1] + bg,  0.f);
                float v2 = fmaxf(acc[i][mt][2] + bg8, 0.f);
                float v3 = fmaxf(acc[i][mt][3] + bg8, 0.f);
                uint32_t h01, l01, h23, l23;
                split_pack(v0, v1, h01, l01);
                split_pack(v2, v3, h23, l23);
                size_t mB = (size_t)(mt * 8 + 2 * t) * 2;
                *(uint32_t*)(sm + ACT_HI_OFF + rowG  + mB) = h01;
                *(uint32_t*)(sm + ACT_LO_OFF + rowG  + mB) = l01;
                *(uint32_t*)(sm + ACT_HI_OFF + rowG8 + mB) = h23;
                *(uint32_t*)(sm + ACT_LO_OFF + rowG8 + mB) = l23;
            }
        }
        __syncthreads();     // writes visible before next layer reads
    }

    // ---- Layer 3 (K=256, N=128) ---------------------------------------------
    #pragma unroll
    for (int mt = 0; mt < 8; mt++)
        #pragma unroll
        for (int q = 0; q < 4; q++) acc[0][mt][q] = 0.f;

    layer_mma<1>(acc, g_wfrag + WF_L3_B32 / 4, warp, 8, actHi, actLo, lane);

    // ---- final epilogue: bias, transpose via f32 scratch, coalesced store ---
    {
        const int nb = warp * 16;
        float bg  = __ldg(b3 + nb + g);
        float bg8 = __ldg(b3 + nb + g + 8);
        __syncthreads();     // all done reading act (scratch overlays it)
        #pragma unroll
        for (int mt = 0; mt < 8; mt++) {
            float2 v01 = make_float2(acc[0][mt][0] + bg,  acc[0][mt][1] + bg);
            float2 v23 = make_float2(acc[0][mt][2] + bg8, acc[0][mt][3] + bg8);
            size_t mB = (size_t)(mt * 8 + 2 * t) * 4;
            *(float2*)(sm + (size_t)(nb + g)     * 272 + mB) = v01;
            *(float2*)(sm + (size_t)(nb + g + 8) * 272 + mB) = v23;
        }
        __syncthreads();
        int mloc = tid >> 2, fgrp = tid & 3;
        int m = m0 + mloc;
        if (m < n) {
            const float* scr = (const float*)sm;
            #pragma unroll
            for (int i = 0; i < 8; i++) {
                int f = fgrp * 32 + i * 4;
                float4 v;
                v.x = scr[(f + 0) * 68 + mloc];
                v.y = scr[(f + 1) * 68 + mloc];
                v.z = scr[(f + 2) * 68 + mloc];
                v.w = scr[(f + 3) * 68 + mloc];
                *(float4*)(out + (size_t)m * D_OUT + f) = v;
            }
        }
    }
}

// ---------------------------------------------------------------------------
// kernel_launch
// Inputs: 0=x [N,128] f32, 1=edge_index [2,E] i32, 2=edge_attr [E,128] f32,
//         3=W1 [256,256], 4=b1, 5=W2 [256,256], 6=b2, 7=W3 [256,128], 8=b3.
// ---------------------------------------------------------------------------
extern "C" void kernel_launch(void* const* d_in, const int* in_sizes, int n_in,
                              void* d_out, int out_size) {
    const float* x  = (const float*)d_in[0];
    const int* ei   = (const int*)d_in[1];
    const float* ea = (const float*)d_in[2];
    const float* W1 = (const float*)d_in[3];
    const float* b1 = (const float*)d_in[4];
    const float* W2 = (const float*)d_in[5];
    const float* b2 = (const float*)d_in[6];
    const float* W3 = (const float*)d_in[7];
    const float* b3 = (const float*)d_in[8];
    float* out = (float*)d_out;

    const int n = in_sizes[0] / D_NODE;              // 100000
    const int n_edges = in_sizes[2] / D_EDGE;        // 1600000
    const int* col = ei + n_edges;                   // edge_index[1]

    // 1) zero scratch (float4 stores)
    {
        int total4 = N_NODES * D_EDGE / 4;
        zero_kernel<<<(total4 + 255) / 256, 256>>>();
    }
    // 2) weight prep (fragment-order split)
    prep_kernel<<<(WF_TOTAL_B32 + 255) / 256, 256>>>(W1, W2, W3);
    // 3) scatter-add + counts (streaming reads, red.v4 atomics)
    {
        long long threads = (long long)n_edges * 32;
        int blocks = (int)((threads + 255) / 256);
        scatter_kernel<<<blocks, 256>>>(col, (const float4*)ea, n_edges);
    }
    // 4) fused tensor-core MLP
    {
        static int smem_set = 0;
        if (!smem_set) {
            cudaFuncSetAttribute(mlp_kernel,
                                 cudaFuncAttributeMaxDynamicSharedMemorySize,
                                 SMEM_BYTES);
            smem_set = 1;
        }
        int blocks = (n + 63) / 64;                  // 1563
        mlp_kernel<<<blocks, 256, SMEM_BYTES>>>(x, b1, b2, b3, out, n);
    }
}

// round 11
// speedup vs baseline: 1.2079x; 1.1303x over previous
#include <cuda_runtime.h>
#include <cuda_fp16.h>
#include <cstdint>

// ---------------------------------------------------------------------------
// Problem constants
// ---------------------------------------------------------------------------
#define N_NODES 100000
#define N_EDGES 1600000
#define D_NODE  128
#define D_EDGE  128
#define D_IN    256
#define HID     256
#define D_OUT   128

// ---------------------------------------------------------------------------
// Scratch (device globals; allocations are forbidden)
// ---------------------------------------------------------------------------
__device__ __align__(16) float g_sum[(size_t)N_NODES * D_EDGE];
__device__ int g_cnt[N_NODES];

// Weight blob in EXACT mma.sync A-fragment order, fp16 hi/lo terms:
//   b32 index = layerBase + ((kstep*NFT + ft)*2 + term)*128 + lane*4 + reg
#define WF_L2_B32 65536
#define WF_L3_B32 131072
#define WF_TOTAL_B32 163840
__device__ __align__(16) uint4 g_wfrag[WF_TOTAL_B32 / 4];

// ---------------------------------------------------------------------------
// SMEM map: single fp16 activation buffer [256 feat][72 f16] stride 144 B.
// L3 f32 transpose scratch (128 x 68 f32, stride 272 B = 34816 B) overlays it.
// ---------------------------------------------------------------------------
#define ACT_OFF 0
#define SMEM_BYTES 36864

// ---------------------------------------------------------------------------
// PTX helpers (arch-portable, valid at compute_103)
// ---------------------------------------------------------------------------
__device__ __forceinline__ uint32_t smem_to_u32(const void* p) {
    uint32_t a;
    asm("{ .reg .u64 t; cvta.to.shared.u64 t, %1; cvt.u32.u64 %0, t; }"
        : "=r"(a) : "l"(p));
    return a;
}

#define LDMX4T(r, addr) \
    asm volatile("ldmatrix.sync.aligned.m8n8.x4.trans.shared.b16 {%0,%1,%2,%3}, [%4];" \
        : "=r"((r)[0]), "=r"((r)[1]), "=r"((r)[2]), "=r"((r)[3]) : "r"(addr))

#define MMA_F16(d, a, b0v, b1v) \
    asm volatile("mma.sync.aligned.m16n8k16.row.col.f32.f16.f16.f32 " \
        "{%0,%1,%2,%3},{%4,%5,%6,%7},{%8,%9},{%0,%1,%2,%3};" \
        : "+f"((d)[0]), "+f"((d)[1]), "+f"((d)[2]), "+f"((d)[3]) \
        : "r"((a)[0]), "r"((a)[1]), "r"((a)[2]), "r"((a)[3]), \
          "r"(b0v), "r"(b1v))

// fp32 pair -> packed f16x2 (a in low half, b in high half)
__device__ __forceinline__ uint32_t pack_f16x2(float a, float b) {
    uint32_t r;
    asm("cvt.rn.f16x2.f32 %0, %1, %2;" : "=r"(r) : "f"(b), "f"(a));
    return r;
}

// ---------------------------------------------------------------------------
// Kernel 1: zero scratch (float4 stores)
// ---------------------------------------------------------------------------
__global__ void zero_kernel() {
    int i = blockIdx.x * blockDim.x + threadIdx.x;
    const int total4 = N_NODES * D_EDGE / 4;
    if (i < total4)
        ((float4*)g_sum)[i] = make_float4(0.f, 0.f, 0.f, 0.f);
    if (i < N_NODES) g_cnt[i] = 0;
}

// ---------------------------------------------------------------------------
// Kernel 2: weight prep — fp16 hi/lo fragments in mma A-operand order.
// wh = fp16(w), wl = fp16(w - wh): together exact to ~2^-22.
// ---------------------------------------------------------------------------
__global__ void prep_kernel(const float* __restrict__ W1,
                            const float* __restrict__ W2,
                            const float* __restrict__ W3) {
    int i = blockIdx.x * blockDim.x + threadIdx.x;
    if (i >= WF_TOTAL_B32) return;
    uint32_t* blob = (uint32_t*)g_wfrag;
    const float* W; int idx, Nl, NFT;
    if (i < WF_L2_B32)      { W = W1; idx = i;             Nl = 256; NFT = 16; }
    else if (i < WF_L3_B32) { W = W2; idx = i - WF_L2_B32; Nl = 256; NFT = 16; }
    else                    { W = W3; idx = i - WF_L3_B32; Nl = 128; NFT = 8;  }
    int reg   = idx & 3;
    int lane  = (idx >> 2) & 31;
    int term  = (idx >> 7) & 1;
    int ft    = (idx >> 8) % NFT;
    int kstep = (idx >> 8) / NFT;
    int r = lane >> 2, t = lane & 3;
    int m = ft * 16 + r + (reg & 1) * 8;
    int k = kstep * 16 + t * 2 + (reg >> 1) * 8;
    float w0 = __ldg(W + (size_t)k * Nl + m);
    float w1 = __ldg(W + (size_t)(k + 1) * Nl + m);
    __half h0 = __float2half_rn(w0);
    __half h1 = __float2half_rn(w1);
    __half l0 = __float2half_rn(w0 - __half2float(h0));
    __half l1 = __float2half_rn(w1 - __half2float(h1));
    uint32_t hi = ((uint32_t)__half_as_ushort(h1) << 16) | __half_as_ushort(h0);
    uint32_t lo = ((uint32_t)__half_as_ushort(l1) << 16) | __half_as_ushort(l0);
    blob[i] = term ? lo : hi;
}

// ---------------------------------------------------------------------------
// Kernel 3: scatter-add (red.v4, streaming reads) + degree count.
// ---------------------------------------------------------------------------
__global__ void __launch_bounds__(256)
scatter_kernel(const int* __restrict__ col,
               const float4* __restrict__ edge_attr,
               int n_edges) {
    long long gid = (long long)blockIdx.x * blockDim.x + threadIdx.x;
    if (gid >= (long long)n_edges * 32) return;
    int e = (int)(gid >> 5);
    int c = (int)(gid & 31);
    int dst = __ldg(col + e);
    if (c == 0) atomicAdd(&g_cnt[dst], 1);
    float4 v = __ldg(edge_attr + (size_t)e * 32 + c);
    float* p = g_sum + (size_t)dst * D_EDGE + c * 4;
    asm volatile("red.global.add.v4.f32 [%0], {%1,%2,%3,%4};"
                 :: "l"(p), "f"(v.x), "f"(v.y), "f"(v.z), "f"(v.w)
                 : "memory");
}

// ---------------------------------------------------------------------------
// Layer MMA: warp = NT*16 feats x 64 nodes. Weights fp16 hi/lo (2 terms),
// activations single fp16. 32 MMAs / 4 LDSM / 2*NT LDG per k-step.
// ---------------------------------------------------------------------------
template<int NT>
__device__ __forceinline__ void layer_mma(
    float acc[2][8][4],
    const uint4* __restrict__ wf,    // layer base (uint4 units)
    int ftBase, int NFT,
    uint32_t act, int lane)
{
    const uint32_t bK  = (uint32_t)(lane & 15);
    const uint32_t bMH = (uint32_t)((lane >> 4) * 8);
    #pragma unroll
    for (int kstep = 0; kstep < 16; kstep++) {
        uint32_t ah[NT][4], al[NT][4];
        #pragma unroll
        for (int i = 0; i < NT; i++) {
            const uint4* p = wf + (size_t)((kstep * NFT + ftBase + i) * 2) * 32 + lane;
            uint4 h = __ldg(p);
            uint4 l = __ldg(p + 32);
            ah[i][0] = h.x; ah[i][1] = h.y; ah[i][2] = h.z; ah[i][3] = h.w;
            al[i][0] = l.x; al[i][1] = l.y; al[i][2] = l.z; al[i][3] = l.w;
        }
        const uint32_t kByte = (uint32_t)(kstep * 16 + (int)bK) * 144u;
        #pragma unroll
        for (int mt = 0; mt < 4; mt++) {
            const uint32_t mByte = (uint32_t)(mt * 16 + (int)bMH) * 2u;
            uint32_t bh[4];
            LDMX4T(bh, act + kByte + mByte);
            #pragma unroll
            for (int i = 0; i < NT; i++) {
                #pragma unroll
                for (int h = 0; h < 2; h++) {
                    MMA_F16(acc[i][mt * 2 + h], ah[i], bh[2 * h], bh[2 * h + 1]);
                    MMA_F16(acc[i][mt * 2 + h], al[i], bh[2 * h], bh[2 * h + 1]);
                }
            }
        }
    }
}

// ---------------------------------------------------------------------------
// Kernel 4: fused 3-layer MLP. CTA = 64 nodes, 256 threads, 2 CTAs/SM.
// ---------------------------------------------------------------------------
__global__ void __launch_bounds__(256, 2)
mlp_kernel(const float* __restrict__ x,
           const float* __restrict__ b1,
           const float* __restrict__ b2,
           const float* __restrict__ b3,
           float* __restrict__ out, int n)
{
    extern __shared__ char sm[];
    const uint32_t sb  = smem_to_u32(sm);
    const uint32_t act = sb + ACT_OFF;

    const int tid  = threadIdx.x;
    const int warp = tid >> 5;
    const int lane = tid & 31;
    const int g    = lane >> 2;
    const int t    = lane & 3;
    const int m0   = blockIdx.x * 64;

    // ---- input fill: act[feat][node] = f16(concat(x, mean)) ----------------
    {
        int r = tid >> 2;           // local node 0..63
        int q = tid & 3;            // feature quarter
        int m = m0 + r;
        bool valid = (m < n);
        float inv = 1.0f;
        if (valid) inv = 1.0f / fmaxf((float)__ldg(&g_cnt[m]), 1.0f);
        const float4* xr = (const float4*)(x + (size_t)(valid ? m : 0) * D_NODE);
        const float4* gr = (const float4*)(g_sum + (size_t)(valid ? m : 0) * D_EDGE);
        #pragma unroll
        for (int j = 0; j < 16; j++) {
            int fb = q * 64 + j * 4;
            float4 v = make_float4(0.f, 0.f, 0.f, 0.f);
            if (valid) {
                if (q < 2) v = __ldg(xr + q * 16 + j);
                else {
                    v = __ldg(gr + (q - 2) * 16 + j);
                    v.x *= inv; v.y *= inv; v.z *= inv; v.w *= inv;
                }
            }
            uint32_t h01 = pack_f16x2(v.x, v.y);
            uint32_t h23 = pack_f16x2(v.z, v.w);
            size_t o0 = (size_t)(fb + 0) * 144 + (size_t)r * 2;
            size_t o1 = (size_t)(fb + 1) * 144 + (size_t)r * 2;
            size_t o2 = (size_t)(fb + 2) * 144 + (size_t)r * 2;
            size_t o3 = (size_t)(fb + 3) * 144 + (size_t)r * 2;
            *(uint16_t*)(sm + ACT_OFF + o0) = (uint16_t)h01;
            *(uint16_t*)(sm + ACT_OFF + o1) = (uint16_t)(h01 >> 16);
            *(uint16_t*)(sm + ACT_OFF + o2) = (uint16_t)h23;
            *(uint16_t*)(sm + ACT_OFF + o3) = (uint16_t)(h23 >> 16);
        }
    }
    __syncthreads();

    float acc[2][8][4];

    // ---- Layers 1 & 2 (K=256, N=256) ---------------------------------------
    #pragma unroll 1
    for (int L = 0; L < 2; L++) {
        const uint4* wf = g_wfrag + (L == 0 ? 0 : WF_L2_B32 / 4);
        #pragma unroll
        for (int i = 0; i < 2; i++)
            #pragma unroll
            for (int mt = 0; mt < 8; mt++)
                #pragma unroll
                for (int q = 0; q < 4; q++) acc[i][mt][q] = 0.f;

        layer_mma<2>(acc, wf, warp * 2, 16, act, lane);

        __syncthreads();     // all warps done READING act for this layer

        const float* bias = (L == 0) ? b1 : b2;
        const int nb = warp * 32;
        #pragma unroll
        for (int i = 0; i < 2; i++) {
            int fb = nb + i * 16;
            float bg  = __ldg(bias + fb + g);
            float bg8 = __ldg(bias + fb + g + 8);
            size_t rowG  = (size_t)(fb + g) * 144;
            size_t rowG8 = (size_t)(fb + g + 8) * 144;
            #pragma unroll
            for (int mt = 0; mt < 8; mt++) {
                float v0 = fmaxf(acc[i][mt][0] + bg,  0.f);
                float v1 = fmaxf(acc[i][mt][1] + bg,  0.f);
                float v2 = fmaxf(acc[i][mt][2] + bg8, 0.f);
                float v3 = fmaxf(acc[i][mt][3] + bg8, 0.f);
                uint32_t h01 = pack_f16x2(v0, v1);
                uint32_t h23 = pack_f16x2(v2, v3);
                size_t mB = (size_t)(mt * 8 + 2 * t) * 2;
                *(uint32_t*)(sm + ACT_OFF + rowG  + mB) = h01;
                *(uint32_t*)(sm + ACT_OFF + rowG8 + mB) = h23;
            }
        }
        __syncthreads();     // writes visible before next layer reads
    }

    // ---- Layer 3 (K=256, N=128) ---------------------------------------------
    #pragma unroll
    for (int mt = 0; mt < 8; mt++)
        #pragma unroll
        for (int q = 0; q < 4; q++) acc[0][mt][q] = 0.f;

    layer_mma<1>(acc, g_wfrag + WF_L3_B32 / 4, warp, 8, act, lane);

    // ---- final epilogue: bias, transpose via f32 scratch, coalesced store ---
    {
        const int nb = warp * 16;
        float bg  = __ldg(b3 + nb + g);
        float bg8 = __ldg(b3 + nb + g + 8);
        __syncthreads();     // all done reading act (scratch overlays it)
        #pragma unroll
        for (int mt = 0; mt < 8; mt++) {
            float2 v01 = make_float2(acc[0][mt][0] + bg,  acc[0][mt][1] + bg);
            float2 v23 = make_float2(acc[0][mt][2] + bg8, acc[0][mt][3] + bg8);
            size_t mB = (size_t)(mt * 8 + 2 * t) * 4;
            *(float2*)(sm + (size_t)(nb + g)     * 272 + mB) = v01;
            *(float2*)(sm + (size_t)(nb + g + 8) * 272 + mB) = v23;
        }
        __syncthreads();
        int mloc = tid >> 2, fgrp = tid & 3;
        int m = m0 + mloc;
        if (m < n) {
            const float* scr = (const float*)sm;
            #pragma unroll
            for (int i = 0; i < 8; i++) {
                int f = fgrp * 32 + i * 4;
                float4 v;
                v.x = scr[(f + 0) * 68 + mloc];
                v.y = scr[(f + 1) * 68 + mloc];
                v.z = scr[(f + 2) * 68 + mloc];
                v.w = scr[(f + 3) * 68 + mloc];
                *(float4*)(out + (size_t)m * D_OUT + f) = v;
            }
        }
    }
}

// ---------------------------------------------------------------------------
// kernel_launch
// Inputs: 0=x [N,128] f32, 1=edge_index [2,E] i32, 2=edge_attr [E,128] f32,
//         3=W1 [256,256], 4=b1, 5=W2 [256,256], 6=b2, 7=W3 [256,128], 8=b3.
// ---------------------------------------------------------------------------
extern "C" void kernel_launch(void* const* d_in, const int* in_sizes, int n_in,
                              void* d_out, int out_size) {
    const float* x  = (const float*)d_in[0];
    const int* ei   = (const int*)d_in[1];
    const float* ea = (const float*)d_in[2];
    const float* W1 = (const float*)d_in[3];
    const float* b1 = (const float*)d_in[4];
    const float* W2 = (const float*)d_in[5];
    const float* b2 = (const float*)d_in[6];
    const float* W3 = (const float*)d_in[7];
    const float* b3 = (const float*)d_in[8];
    float* out = (float*)d_out;

    const int n = in_sizes[0] / D_NODE;              // 100000
    const int n_edges = in_sizes[2] / D_EDGE;        // 1600000
    const int* col = ei + n_edges;                   // edge_index[1]

    // 1) zero scratch (float4 stores)
    {
        int total4 = N_NODES * D_EDGE / 4;
        zero_kernel<<<(total4 + 255) / 256, 256>>>();
    }
    // 2) weight prep (fp16 hi/lo fragment-order split)
    prep_kernel<<<(WF_TOTAL_B32 + 255) / 256, 256>>>(W1, W2, W3);
    // 3) scatter-add + counts (streaming reads, red.v4 atomics)
    {
        long long threads = (long long)n_edges * 32;
        int blocks = (int)((threads + 255) / 256);
        scatter_kernel<<<blocks, 256>>>(col, (const float4*)ea, n_edges);
    }
    // 4) fused tensor-core MLP
    {
        static int smem_set = 0;
        if (!smem_set) {
            cudaFuncSetAttribute(mlp_kernel,
                                 cudaFuncAttributeMaxDynamicSharedMemorySize,
                                 SMEM_BYTES);
            smem_set = 1;
        }
        int blocks = (n + 63) / 64;                  // 1563
        mlp_kernel<<<blocks, 256, SMEM_BYTES>>>(x, b1, b2, b3, out, n);
    }
}

// round 12
// speedup vs baseline: 1.3466x; 1.1148x over previous
#include <cuda_runtime.h>
#include <cuda_fp16.h>
#include <cstdint>

// ---------------------------------------------------------------------------
// Problem constants
// ---------------------------------------------------------------------------
#define N_NODES 100000
#define N_EDGES 1600000
#define D_NODE  128
#define D_EDGE  128
#define D_IN    256
#define HID     256
#define D_OUT   128

// ---------------------------------------------------------------------------
// Scratch (device globals; allocations are forbidden)
// ---------------------------------------------------------------------------
__device__ __align__(16) float g_sum[(size_t)N_NODES * D_EDGE];
__device__ int g_cnt[N_NODES];

// Weight blob in EXACT mma.sync A-fragment order, single fp16 term:
//   b32 index = layerBase + (kstep*NFT + ft)*128 + lane*4 + reg
#define WF_L2_B32 32768
#define WF_L3_B32 65536
#define WF_TOTAL_B32 81920
__device__ __align__(16) uint4 g_wfrag[WF_TOTAL_B32 / 4];

// ---------------------------------------------------------------------------
// SMEM map: single fp16 activation buffer [256 feat][72 f16] stride 144 B.
// L3 f32 transpose scratch (128 x 68 f32, stride 272 B = 34816 B) overlays it.
// ---------------------------------------------------------------------------
#define ACT_OFF 0
#define SMEM_BYTES 36864

// ---------------------------------------------------------------------------
// PTX helpers (arch-portable, valid at compute_103)
// ---------------------------------------------------------------------------
__device__ __forceinline__ uint32_t smem_to_u32(const void* p) {
    uint32_t a;
    asm("{ .reg .u64 t; cvta.to.shared.u64 t, %1; cvt.u32.u64 %0, t; }"
        : "=r"(a) : "l"(p));
    return a;
}

#define LDMX4T(r, addr) \
    asm volatile("ldmatrix.sync.aligned.m8n8.x4.trans.shared.b16 {%0,%1,%2,%3}, [%4];" \
        : "=r"((r)[0]), "=r"((r)[1]), "=r"((r)[2]), "=r"((r)[3]) : "r"(addr))

#define MMA_F16(d, a, b0v, b1v) \
    asm volatile("mma.sync.aligned.m16n8k16.row.col.f32.f16.f16.f32 " \
        "{%0,%1,%2,%3},{%4,%5,%6,%7},{%8,%9},{%0,%1,%2,%3};" \
        : "+f"((d)[0]), "+f"((d)[1]), "+f"((d)[2]), "+f"((d)[3]) \
        : "r"((a)[0]), "r"((a)[1]), "r"((a)[2]), "r"((a)[3]), \
          "r"(b0v), "r"(b1v))

// fp32 pair -> packed f16x2 (a in low half, b in high half)
__device__ __forceinline__ uint32_t pack_f16x2(float a, float b) {
    uint32_t r;
    asm("cvt.rn.f16x2.f32 %0, %1, %2;" : "=r"(r) : "f"(b), "f"(a));
    return r;
}

// ---------------------------------------------------------------------------
// Kernel 1: zero scratch (float4 stores)
// ---------------------------------------------------------------------------
__global__ void zero_kernel() {
    int i = blockIdx.x * blockDim.x + threadIdx.x;
    const int total4 = N_NODES * D_EDGE / 4;
    if (i < total4)
        ((float4*)g_sum)[i] = make_float4(0.f, 0.f, 0.f, 0.f);
    if (i < N_NODES) g_cnt[i] = 0;
}

// ---------------------------------------------------------------------------
// Kernel 2: weight prep — single fp16 term, mma A-fragment order
// ---------------------------------------------------------------------------
__global__ void prep_kernel(const float* __restrict__ W1,
                            const float* __restrict__ W2,
                            const float* __restrict__ W3) {
    int i = blockIdx.x * blockDim.x + threadIdx.x;
    if (i >= WF_TOTAL_B32) return;
    uint32_t* blob = (uint32_t*)g_wfrag;
    const float* W; int idx, Nl, NFT;
    if (i < WF_L2_B32)      { W = W1; idx = i;             Nl = 256; NFT = 16; }
    else if (i < WF_L3_B32) { W = W2; idx = i - WF_L2_B32; Nl = 256; NFT = 16; }
    else                    { W = W3; idx = i - WF_L3_B32; Nl = 128; NFT = 8;  }
    int reg   = idx & 3;
    int lane  = (idx >> 2) & 31;
    int ft    = (idx >> 7) % NFT;
    int kstep = (idx >> 7) / NFT;
    int r = lane >> 2, t = lane & 3;
    int m = ft * 16 + r + (reg & 1) * 8;
    int k = kstep * 16 + t * 2 + (reg >> 1) * 8;
    float w0 = __ldg(W + (size_t)k * Nl + m);
    float w1 = __ldg(W + (size_t)(k + 1) * Nl + m);
    blob[i] = pack_f16x2(w0, w1);
}

// ---------------------------------------------------------------------------
// Kernel 3: scatter-add (red.v4, streaming reads) + degree count.
// ---------------------------------------------------------------------------
__global__ void __launch_bounds__(256)
scatter_kernel(const int* __restrict__ col,
               const float4* __restrict__ edge_attr,
               int n_edges) {
    long long gid = (long long)blockIdx.x * blockDim.x + threadIdx.x;
    if (gid >= (long long)n_edges * 32) return;
    int e = (int)(gid >> 5);
    int c = (int)(gid & 31);
    int dst = __ldg(col + e);
    if (c == 0) atomicAdd(&g_cnt[dst], 1);
    float4 v = __ldg(edge_attr + (size_t)e * 32 + c);
    float* p = g_sum + (size_t)dst * D_EDGE + c * 4;
    asm volatile("red.global.add.v4.f32 [%0], {%1,%2,%3,%4};"
                 :: "l"(p), "f"(v.x), "f"(v.y), "f"(v.z), "f"(v.w)
                 : "memory");
}

// ---------------------------------------------------------------------------
// Layer MMA: warp = NT*16 feats x 64 nodes. Single fp16 weight term,
// single fp16 activations. 16 MMAs / 4 LDSM / NT LDG per k-step (NT=2).
// ---------------------------------------------------------------------------
template<int NT>
__device__ __forceinline__ void layer_mma(
    float acc[2][8][4],
    const uint4* __restrict__ wf,    // layer base (uint4 units)
    int ftBase, int NFT,
    uint32_t act, int lane)
{
    const uint32_t bK  = (uint32_t)(lane & 15);
    const uint32_t bMH = (uint32_t)((lane >> 4) * 8);
    #pragma unroll
    for (int kstep = 0; kstep < 16; kstep++) {
        uint32_t ah[NT][4];
        #pragma unroll
        for (int i = 0; i < NT; i++) {
            const uint4* p = wf + (size_t)(kstep * NFT + ftBase + i) * 32 + lane;
            uint4 h = __ldg(p);
            ah[i][0] = h.x; ah[i][1] = h.y; ah[i][2] = h.z; ah[i][3] = h.w;
        }
        const uint32_t kByte = (uint32_t)(kstep * 16 + (int)bK) * 144u;
        #pragma unroll
        for (int mt = 0; mt < 4; mt++) {
            const uint32_t mByte = (uint32_t)(mt * 16 + (int)bMH) * 2u;
            uint32_t bh[4];
            LDMX4T(bh, act + kByte + mByte);
            #pragma unroll
            for (int i = 0; i < NT; i++) {
                #pragma unroll
                for (int h = 0; h < 2; h++) {
                    MMA_F16(acc[i][mt * 2 + h], ah[i], bh[2 * h], bh[2 * h + 1]);
                }
            }
        }
    }
}

// ---------------------------------------------------------------------------
// Kernel 4: fused 3-layer MLP. CTA = 64 nodes, 256 threads, 2 CTAs/SM.
// ---------------------------------------------------------------------------
__global__ void __launch_bounds__(256, 2)
mlp_kernel(const float* __restrict__ x,
           const float* __restrict__ b1,
           const float* __restrict__ b2,
           const float* __restrict__ b3,
           float* __restrict__ out, int n)
{
    extern __shared__ char sm[];
    const uint32_t sb  = smem_to_u32(sm);
    const uint32_t act = sb + ACT_OFF;

    const int tid  = threadIdx.x;
    const int warp = tid >> 5;
    const int lane = tid & 31;
    const int g    = lane >> 2;
    const int t    = lane & 3;
    const int m0   = blockIdx.x * 64;

    // ---- input fill: act[feat][node] = f16(concat(x, mean)) ----------------
    {
        int r = tid >> 2;           // local node 0..63
        int q = tid & 3;            // feature quarter
        int m = m0 + r;
        bool valid = (m < n);
        float inv = 1.0f;
        if (valid) inv = 1.0f / fmaxf((float)__ldg(&g_cnt[m]), 1.0f);
        const float4* xr = (const float4*)(x + (size_t)(valid ? m : 0) * D_NODE);
        const float4* gr = (const float4*)(g_sum + (size_t)(valid ? m : 0) * D_EDGE);
        #pragma unroll
        for (int j = 0; j < 16; j++) {
            int fb = q * 64 + j * 4;
            float4 v = make_float4(0.f, 0.f, 0.f, 0.f);
            if (valid) {
                if (q < 2) v = __ldg(xr + q * 16 + j);
                else {
                    v = __ldg(gr + (q - 2) * 16 + j);
                    v.x *= inv; v.y *= inv; v.z *= inv; v.w *= inv;
                }
            }
            uint32_t h01 = pack_f16x2(v.x, v.y);
            uint32_t h23 = pack_f16x2(v.z, v.w);
            size_t o0 = (size_t)(fb + 0) * 144 + (size_t)r * 2;
            size_t o1 = (size_t)(fb + 1) * 144 + (size_t)r * 2;
            size_t o2 = (size_t)(fb + 2) * 144 + (size_t)r * 2;
            size_t o3 = (size_t)(fb + 3) * 144 + (size_t)r * 2;
            *(uint16_t*)(sm + ACT_OFF + o0) = (uint16_t)h01;
            *(uint16_t*)(sm + ACT_OFF + o1) = (uint16_t)(h01 >> 16);
            *(uint16_t*)(sm + ACT_OFF + o2) = (uint16_t)h23;
            *(uint16_t*)(sm + ACT_OFF + o3) = (uint16_t)(h23 >> 16);
        }
    }
    __syncthreads();

    float acc[2][8][4];

    // ---- Layers 1 & 2 (K=256, N=256) ---------------------------------------
    #pragma unroll 1
    for (int L = 0; L < 2; L++) {
        const uint4* wf = g_wfrag + (L == 0 ? 0 : WF_L2_B32 / 4);
        #pragma unroll
        for (int i = 0; i < 2; i++)
            #pragma unroll
            for (int mt = 0; mt < 8; mt++)
                #pragma unroll
                for (int q = 0; q < 4; q++) acc[i][mt][q] = 0.f;

        layer_mma<2>(acc, wf, warp * 2, 16, act, lane);

        __syncthreads();     // all warps done READING act for this layer

        const float* bias = (L == 0) ? b1 : b2;
        const int nb = warp * 32;
        #pragma unroll
        for (int i = 0; i < 2; i++) {
            int fb = nb + i * 16;
            float bg  = __ldg(bias + fb + g);
            float bg8 = __ldg(bias + fb + g + 8);
            size_t rowG  = (size_t)(fb + g) * 144;
            size_t rowG8 = (size_t)(fb + g + 8) * 144;
            #pragma unroll
            for (int mt = 0; mt < 8; mt++) {
                float v0 = fmaxf(acc[i][mt][0] + bg,  0.f);
                float v1 = fmaxf(acc[i][mt][1] + bg,  0.f);
                float v2 = fmaxf(acc[i][mt][2] + bg8, 0.f);
                float v3 = fmaxf(acc[i][mt][3] + bg8, 0.f);
                uint32_t h01 = pack_f16x2(v0, v1);
                uint32_t h23 = pack_f16x2(v2, v3);
                size_t mB = (size_t)(mt * 8 + 2 * t) * 2;
                *(uint32_t*)(sm + ACT_OFF + rowG  + mB) = h01;
                *(uint32_t*)(sm + ACT_OFF + rowG8 + mB) = h23;
            }
        }
        __syncthreads();     // writes visible before next layer reads
    }

    // ---- Layer 3 (K=256, N=128) ---------------------------------------------
    #pragma unroll
    for (int mt = 0; mt < 8; mt++)
        #pragma unroll
        for (int q = 0; q < 4; q++) acc[0][mt][q] = 0.f;

    layer_mma<1>(acc, g_wfrag + WF_L3_B32 / 4, warp, 8, act, lane);

    // ---- final epilogue: bias, transpose via f32 scratch, coalesced store ---
    {
        const int nb = warp * 16;
        float bg  = __ldg(b3 + nb + g);
        float bg8 = __ldg(b3 + nb + g + 8);
        __syncthreads();     // all done reading act (scratch overlays it)
        #pragma unroll
        for (int mt = 0; mt < 8; mt++) {
            float2 v01 = make_float2(acc[0][mt][0] + bg,  acc[0][mt][1] + bg);
            float2 v23 = make_float2(acc[0][mt][2] + bg8, acc[0][mt][3] + bg8);
            size_t mB = (size_t)(mt * 8 + 2 * t) * 4;
            *(float2*)(sm + (size_t)(nb + g)     * 272 + mB) = v01;
            *(float2*)(sm + (size_t)(nb + g + 8) * 272 + mB) = v23;
        }
        __syncthreads();
        int mloc = tid >> 2, fgrp = tid & 3;
        int m = m0 + mloc;
        if (m < n) {
            const float* scr = (const float*)sm;
            #pragma unroll
            for (int i = 0; i < 8; i++) {
                int f = fgrp * 32 + i * 4;
                float4 v;
                v.x = scr[(f + 0) * 68 + mloc];
                v.y = scr[(f + 1) * 68 + mloc];
                v.z = scr[(f + 2) * 68 + mloc];
                v.w = scr[(f + 3) * 68 + mloc];
                *(float4*)(out + (size_t)m * D_OUT + f) = v;
            }
        }
    }
}

// ---------------------------------------------------------------------------
// kernel_launch
// Inputs: 0=x [N,128] f32, 1=edge_index [2,E] i32, 2=edge_attr [E,128] f32,
//         3=W1 [256,256], 4=b1, 5=W2 [256,256], 6=b2, 7=W3 [256,128], 8=b3.
// ---------------------------------------------------------------------------
extern "C" void kernel_launch(void* const* d_in, const int* in_sizes, int n_in,
                              void* d_out, int out_size) {
    const float* x  = (const float*)d_in[0];
    const int* ei   = (const int*)d_in[1];
    const float* ea = (const float*)d_in[2];
    const float* W1 = (const float*)d_in[3];
    const float* b1 = (const float*)d_in[4];
    const float* W2 = (const float*)d_in[5];
    const float* b2 = (const float*)d_in[6];
    const float* W3 = (const float*)d_in[7];
    const float* b3 = (const float*)d_in[8];
    float* out = (float*)d_out;

    const int n = in_sizes[0] / D_NODE;              // 100000
    const int n_edges = in_sizes[2] / D_EDGE;        // 1600000
    const int* col = ei + n_edges;                   // edge_index[1]

    // 1) zero scratch (float4 stores)
    {
        int total4 = N_NODES * D_EDGE / 4;
        zero_kernel<<<(total4 + 255) / 256, 256>>>();
    }
    // 2) weight prep (single fp16 term, fragment order)
    prep_kernel<<<(WF_TOTAL_B32 + 255) / 256, 256>>>(W1, W2, W3);
    // 3) scatter-add + counts (streaming reads, red.v4 atomics)
    {
        long long threads = (long long)n_edges * 32;
        int blocks = (int)((threads + 255) / 256);
        scatter_kernel<<<blocks, 256>>>(col, (const float4*)ea, n_edges);
    }
    // 4) fused tensor-core MLP
    {
        static int smem_set = 0;
        if (!smem_set) {
            cudaFuncSetAttribute(mlp_kernel,
                                 cudaFuncAttributeMaxDynamicSharedMemorySize,
                                 SMEM_BYTES);
            smem_set = 1;
        }
        int blocks = (n + 63) / 64;                  // 1563
        mlp_kernel<<<blocks, 256, SMEM_BYTES>>>(x, b1, b2, b3, out, n);
    }
}

// round 13
// speedup vs baseline: 1.5524x; 1.1529x over previous
#include <cuda_runtime.h>
#include <cuda_fp16.h>
#include <cstdint>

// ---------------------------------------------------------------------------
// Problem constants
// ---------------------------------------------------------------------------
#define N_NODES 100000
#define N_EDGES 1600000
#define D_NODE  128
#define D_EDGE  128
#define D_IN    256
#define HID     256
#define D_OUT   128

// ---------------------------------------------------------------------------
// Scratch (device globals; allocations are forbidden)
// ---------------------------------------------------------------------------
__device__ __align__(16) float g_sum[(size_t)N_NODES * D_EDGE];
__device__ int g_cnt[N_NODES];

// Weight blob in EXACT mma.sync A-fragment order, single fp16 term:
//   b32 index = layerBase + (kstep*NFT + ft)*128 + lane*4 + reg
#define WF_L2_B32 32768
#define WF_L3_B32 65536
#define WF_TOTAL_B32 81920
__device__ __align__(16) uint4 g_wfrag[WF_TOTAL_B32 / 4];

// ---------------------------------------------------------------------------
// SMEM map (MLP): single fp16 activation buffer [256 feat][72 f16], 144 B row.
// L3 f32 transpose scratch (128 x 68 f32, stride 272 B) overlays it.
// ---------------------------------------------------------------------------
#define ACT_OFF 0
#define SMEM_BYTES 36864

// ---------------------------------------------------------------------------
// PTX helpers (arch-portable, valid at compute_103)
// ---------------------------------------------------------------------------
__device__ __forceinline__ uint32_t smem_to_u32(const void* p) {
    uint32_t a;
    asm("{ .reg .u64 t; cvta.to.shared.u64 t, %1; cvt.u32.u64 %0, t; }"
        : "=r"(a) : "l"(p));
    return a;
}

#define LDMX4T(r, addr) \
    asm volatile("ldmatrix.sync.aligned.m8n8.x4.trans.shared.b16 {%0,%1,%2,%3}, [%4];" \
        : "=r"((r)[0]), "=r"((r)[1]), "=r"((r)[2]), "=r"((r)[3]) : "r"(addr))

#define MMA_F16(d, a, b0v, b1v) \
    asm volatile("mma.sync.aligned.m16n8k16.row.col.f32.f16.f16.f32 " \
        "{%0,%1,%2,%3},{%4,%5,%6,%7},{%8,%9},{%0,%1,%2,%3};" \
        : "+f"((d)[0]), "+f"((d)[1]), "+f"((d)[2]), "+f"((d)[3]) \
        : "r"((a)[0]), "r"((a)[1]), "r"((a)[2]), "r"((a)[3]), \
          "r"(b0v), "r"(b1v))

// fp32 pair -> packed f16x2 (a in low half, b in high half)
__device__ __forceinline__ uint32_t pack_f16x2(float a, float b) {
    uint32_t r;
    asm("cvt.rn.f16x2.f32 %0, %1, %2;" : "=r"(r) : "f"(b), "f"(a));
    return r;
}

// ---------------------------------------------------------------------------
// Kernel 1: zero scratch (float4 stores)
// ---------------------------------------------------------------------------
__global__ void zero_kernel() {
    int i = blockIdx.x * blockDim.x + threadIdx.x;
    const int total4 = N_NODES * D_EDGE / 4;
    if (i < total4)
        ((float4*)g_sum)[i] = make_float4(0.f, 0.f, 0.f, 0.f);
    if (i < N_NODES) g_cnt[i] = 0;
}

// ---------------------------------------------------------------------------
// Kernel 2: weight prep — single fp16 term, mma A-fragment order
// ---------------------------------------------------------------------------
__global__ void prep_kernel(const float* __restrict__ W1,
                            const float* __restrict__ W2,
                            const float* __restrict__ W3) {
    int i = blockIdx.x * blockDim.x + threadIdx.x;
    if (i >= WF_TOTAL_B32) return;
    uint32_t* blob = (uint32_t*)g_wfrag;
    const float* W; int idx, Nl, NFT;
    if (i < WF_L2_B32)      { W = W1; idx = i;             Nl = 256; NFT = 16; }
    else if (i < WF_L3_B32) { W = W2; idx = i - WF_L2_B32; Nl = 256; NFT = 16; }
    else                    { W = W3; idx = i - WF_L3_B32; Nl = 128; NFT = 8;  }
    int reg   = idx & 3;
    int lane  = (idx >> 2) & 31;
    int ft    = (idx >> 7) % NFT;
    int kstep = (idx >> 7) / NFT;
    int r = lane >> 2, t = lane & 3;
    int m = ft * 16 + r + (reg & 1) * 8;
    int k = kstep * 16 + t * 2 + (reg >> 1) * 8;
    float w0 = __ldg(W + (size_t)k * Nl + m);
    float w1 = __ldg(W + (size_t)(k + 1) * Nl + m);
    blob[i] = pack_f16x2(w0, w1);
}

// ---------------------------------------------------------------------------
// Kernel 3a: bulk scatter. CTA = 64 edges, 8 warps (8 edges/warp).
// Warp stages 8 edge rows (4 KB) in smem, then 8 lanes each issue ONE
// cp.reduce.async.bulk (512 B, 128 f32 adds offloaded to LTS).
// Issue cost ~4.5 instr/edge vs 64 for per-lane red.v4.
// ---------------------------------------------------------------------------
#define EPB 64          // edges per block
__global__ void __launch_bounds__(256)
scatter_bulk_kernel(const int* __restrict__ col,
                    const float4* __restrict__ edge_attr) {
    extern __shared__ __align__(512) char sbuf[];   // 32 KB: 64 x 512 B rows
    const int tid  = threadIdx.x;
    const int warp = tid >> 5;
    const int lane = tid & 31;
    const int e0   = blockIdx.x * EPB + warp * 8;   // warp's first edge

    // warp-cooperative copy: 8 edge rows = 256 float4
    const float4* src = edge_attr + (size_t)e0 * 32;
    float4* dst = (float4*)(sbuf + warp * 4096);
    #pragma unroll
    for (int i = 0; i < 8; i++)
        dst[i * 32 + lane] = __ldg(src + i * 32 + lane);
    __syncwarp();
    asm volatile("fence.proxy.async.shared::cta;" ::: "memory");

    if (lane < 8) {
        int e = e0 + lane;
        int d = __ldg(col + e);
        atomicAdd(&g_cnt[d], 1);
        uint32_t saddr = smem_to_u32(sbuf + warp * 4096 + lane * 512);
        asm volatile(
            "cp.reduce.async.bulk.global.shared::cta.bulk_group.add.f32 "
            "[%0], [%1], 512;"
            :: "l"(g_sum + (size_t)d * D_EDGE), "r"(saddr) : "memory");
        asm volatile("cp.async.bulk.commit_group;" ::: "memory");
        // must drain before CTA exit (smem may be reallocated)
        asm volatile("cp.async.bulk.wait_group 0;" ::: "memory");
    }
}

// ---------------------------------------------------------------------------
// Kernel 3b: tail scatter (red.v4) for edges not covered by full batches.
// ---------------------------------------------------------------------------
__global__ void __launch_bounds__(256)
scatter_tail_kernel(const int* __restrict__ col,
                    const float4* __restrict__ edge_attr,
                    int start, int n_edges) {
    long long gid = (long long)blockIdx.x * blockDim.x + threadIdx.x;
    int cnt = n_edges - start;
    if (gid >= (long long)cnt * 32) return;
    int e = start + (int)(gid >> 5);
    int c = (int)(gid & 31);
    int dst = __ldg(col + e);
    if (c == 0) atomicAdd(&g_cnt[dst], 1);
    float4 v = __ldg(edge_attr + (size_t)e * 32 + c);
    float* p = g_sum + (size_t)dst * D_EDGE + c * 4;
    asm volatile("red.global.add.v4.f32 [%0], {%1,%2,%3,%4};"
                 :: "l"(p), "f"(v.x), "f"(v.y), "f"(v.z), "f"(v.w)
                 : "memory");
}

// ---------------------------------------------------------------------------
// Layer MMA: warp = NT*16 feats x 64 nodes. Single fp16 weights + acts.
// ---------------------------------------------------------------------------
template<int NT>
__device__ __forceinline__ void layer_mma(
    float acc[2][8][4],
    const uint4* __restrict__ wf,
    int ftBase, int NFT,
    uint32_t act, int lane)
{
    const uint32_t bK  = (uint32_t)(lane & 15);
    const uint32_t bMH = (uint32_t)((lane >> 4) * 8);
    #pragma unroll
    for (int kstep = 0; kstep < 16; kstep++) {
        uint32_t ah[NT][4];
        #pragma unroll
        for (int i = 0; i < NT; i++) {
            const uint4* p = wf + (size_t)(kstep * NFT + ftBase + i) * 32 + lane;
            uint4 h = __ldg(p);
            ah[i][0] = h.x; ah[i][1] = h.y; ah[i][2] = h.z; ah[i][3] = h.w;
        }
        const uint32_t kByte = (uint32_t)(kstep * 16 + (int)bK) * 144u;
        #pragma unroll
        for (int mt = 0; mt < 4; mt++) {
            const uint32_t mByte = (uint32_t)(mt * 16 + (int)bMH) * 2u;
            uint32_t bh[4];
            LDMX4T(bh, act + kByte + mByte);
            #pragma unroll
            for (int i = 0; i < NT; i++) {
                #pragma unroll
                for (int h = 0; h < 2; h++) {
                    MMA_F16(acc[i][mt * 2 + h], ah[i], bh[2 * h], bh[2 * h + 1]);
                }
            }
        }
    }
}

// ---------------------------------------------------------------------------
// Kernel 4: fused 3-layer MLP. CTA = 64 nodes, 256 threads, 2 CTAs/SM.
// ---------------------------------------------------------------------------
__global__ void __launch_bounds__(256, 2)
mlp_kernel(const float* __restrict__ x,
           const float* __restrict__ b1,
           const float* __restrict__ b2,
           const float* __restrict__ b3,
           float* __restrict__ out, int n)
{
    extern __shared__ char sm[];
    const uint32_t sb  = smem_to_u32(sm);
    const uint32_t act = sb + ACT_OFF;

    const int tid  = threadIdx.x;
    const int warp = tid >> 5;
    const int lane = tid & 31;
    const int g    = lane >> 2;
    const int t    = lane & 3;
    const int m0   = blockIdx.x * 64;

    // ---- input fill: act[feat][node] = f16(concat(x, mean)) ----------------
    {
        int r = tid >> 2;           // local node 0..63
        int q = tid & 3;            // feature quarter
        int m = m0 + r;
        bool valid = (m < n);
        float inv = 1.0f;
        if (valid) inv = 1.0f / fmaxf((float)__ldg(&g_cnt[m]), 1.0f);
        const float4* xr = (const float4*)(x + (size_t)(valid ? m : 0) * D_NODE);
        const float4* gr = (const float4*)(g_sum + (size_t)(valid ? m : 0) * D_EDGE);
        #pragma unroll
        for (int j = 0; j < 16; j++) {
            int fb = q * 64 + j * 4;
            float4 v = make_float4(0.f, 0.f, 0.f, 0.f);
            if (valid) {
                if (q < 2) v = __ldg(xr + q * 16 + j);
                else {
                    v = __ldg(gr + (q - 2) * 16 + j);
                    v.x *= inv; v.y *= inv; v.z *= inv; v.w *= inv;
                }
            }
            uint32_t h01 = pack_f16x2(v.x, v.y);
            uint32_t h23 = pack_f16x2(v.z, v.w);
            size_t o0 = (size_t)(fb + 0) * 144 + (size_t)r * 2;
            size_t o1 = (size_t)(fb + 1) * 144 + (size_t)r * 2;
            size_t o2 = (size_t)(fb + 2) * 144 + (size_t)r * 2;
            size_t o3 = (size_t)(fb + 3) * 144 + (size_t)r * 2;
            *(uint16_t*)(sm + ACT_OFF + o0) = (uint16_t)h01;
            *(uint16_t*)(sm + ACT_OFF + o1) = (uint16_t)(h01 >> 16);
            *(uint16_t*)(sm + ACT_OFF + o2) = (uint16_t)h23;
            *(uint16_t*)(sm + ACT_OFF + o3) = (uint16_t)(h23 >> 16);
        }
    }
    __syncthreads();

    float acc[2][8][4];

    // ---- Layers 1 & 2 (K=256, N=256) ---------------------------------------
    #pragma unroll 1
    for (int L = 0; L < 2; L++) {
        const uint4* wf = g_wfrag + (L == 0 ? 0 : WF_L2_B32 / 4);
        #pragma unroll
        for (int i = 0; i < 2; i++)
            #pragma unroll
            for (int mt = 0; mt < 8; mt++)
                #pragma unroll
                for (int q = 0; q < 4; q++) acc[i][mt][q] = 0.f;

        layer_mma<2>(acc, wf, warp * 2, 16, act, lane);

        __syncthreads();     // all warps done READING act for this layer

        const float* bias = (L == 0) ? b1 : b2;
        const int nb = warp * 32;
        #pragma unroll
        for (int i = 0; i < 2; i++) {
            int fb = nb + i * 16;
            float bg  = __ldg(bias + fb + g);
            float bg8 = __ldg(bias + fb + g + 8);
            size_t rowG  = (size_t)(fb + g) * 144;
            size_t rowG8 = (size_t)(fb + g + 8) * 144;
            #pragma unroll
            for (int mt = 0; mt < 8; mt++) {
                float v0 = fmaxf(acc[i][mt][0] + bg,  0.f);
                float v1 = fmaxf(acc[i][mt][1] + bg,  0.f);
                float v2 = fmaxf(acc[i][mt][2] + bg8, 0.f);
                float v3 = fmaxf(acc[i][mt][3] + bg8, 0.f);
                uint32_t h01 = pack_f16x2(v0, v1);
                uint32_t h23 = pack_f16x2(v2, v3);
                size_t mB = (size_t)(mt * 8 + 2 * t) * 2;
                *(uint32_t*)(sm + ACT_OFF + rowG  + mB) = h01;
                *(uint32_t*)(sm + ACT_OFF + rowG8 + mB) = h23;
            }
        }
        __syncthreads();     // writes visible before next layer reads
    }

    // ---- Layer 3 (K=256, N=128) ---------------------------------------------
    #pragma unroll
    for (int mt = 0; mt < 8; mt++)
        #pragma unroll
        for (int q = 0; q < 4; q++) acc[0][mt][q] = 0.f;

    layer_mma<1>(acc, g_wfrag + WF_L3_B32 / 4, warp, 8, act, lane);

    // ---- final epilogue: bias, transpose via f32 scratch, coalesced store ---
    {
        const int nb = warp * 16;
        float bg  = __ldg(b3 + nb + g);
        float bg8 = __ldg(b3 + nb + g + 8);
        __syncthreads();     // all done reading act (scratch overlays it)
        #pragma unroll
        for (int mt = 0; mt < 8; mt++) {
            float2 v01 = make_float2(acc[0][mt][0] + bg,  acc[0][mt][1] + bg);
            float2 v23 = make_float2(acc[0][mt][2] + bg8, acc[0][mt][3] + bg8);
            size_t mB = (size_t)(mt * 8 + 2 * t) * 4;
            *(float2*)(sm + (size_t)(nb + g)     * 272 + mB) = v01;
            *(float2*)(sm + (size_t)(nb + g + 8) * 272 + mB) = v23;
        }
        __syncthreads();
        int mloc = tid >> 2, fgrp = tid & 3;
        int m = m0 + mloc;
        if (m < n) {
            const float* scr = (const float*)sm;
            #pragma unroll
            for (int i = 0; i < 8; i++) {
                int f = fgrp * 32 + i * 4;
                float4 v;
                v.x = scr[(f + 0) * 68 + mloc];
                v.y = scr[(f + 1) * 68 + mloc];
                v.z = scr[(f + 2) * 68 + mloc];
                v.w = scr[(f + 3) * 68 + mloc];
                *(float4*)(out + (size_t)m * D_OUT + f) = v;
            }
        }
    }
}

// ---------------------------------------------------------------------------
// kernel_launch
// Inputs: 0=x [N,128] f32, 1=edge_index [2,E] i32, 2=edge_attr [E,128] f32,
//         3=W1 [256,256], 4=b1, 5=W2 [256,256], 6=b2, 7=W3 [256,128], 8=b3.
// ---------------------------------------------------------------------------
extern "C" void kernel_launch(void* const* d_in, const int* in_sizes, int n_in,
                              void* d_out, int out_size) {
    const float* x  = (const float*)d_in[0];
    const int* ei   = (const int*)d_in[1];
    const float* ea = (const float*)d_in[2];
    const float* W1 = (const float*)d_in[3];
    const float* b1 = (const float*)d_in[4];
    const float* W2 = (const float*)d_in[5];
    const float* b2 = (const float*)d_in[6];
    const float* W3 = (const float*)d_in[7];
    const float* b3 = (const float*)d_in[8];
    float* out = (float*)d_out;

    const int n = in_sizes[0] / D_NODE;              // 100000
    const int n_edges = in_sizes[2] / D_EDGE;        // 1600000
    const int* col = ei + n_edges;                   // edge_index[1]

    // 1) zero scratch (float4 stores)
    {
        int total4 = N_NODES * D_EDGE / 4;
        zero_kernel<<<(total4 + 255) / 256, 256>>>();
    }
    // 2) weight prep (single fp16 term, fragment order)
    prep_kernel<<<(WF_TOTAL_B32 + 255) / 256, 256>>>(W1, W2, W3);
    // 3) scatter: bulk TMA reduction for full 64-edge batches + red.v4 tail
    {
        int full = n_edges / EPB;
        if (full > 0)
            scatter_bulk_kernel<<<full, 256, EPB * 512>>>(col, (const float4*)ea);
        int start = full * EPB;
        if (start < n_edges) {
            long long threads = (long long)(n_edges - start) * 32;
            int blocks = (int)((threads + 255) / 256);
            scatter_tail_kernel<<<blocks, 256>>>(col, (const float4*)ea,
                                                 start, n_edges);
        }
    }
    // 4) fused tensor-core MLP
    {
        static int smem_set = 0;
        if (!smem_set) {
            cudaFuncSetAttribute(mlp_kernel,
                                 cudaFuncAttributeMaxDynamicSharedMemorySize,
                                 SMEM_BYTES);
            smem_set = 1;
        }
        int blocks = (n + 63) / 64;                  // 1563
        mlp_kernel<<<blocks, 256, SMEM_BYTES>>>(x, b1, b2, b3, out, n);
    }
}

// round 14
// speedup vs baseline: 1.5812x; 1.0185x over previous
#include <cuda_runtime.h>
#include <cuda_fp16.h>
#include <cstdint>

// ---------------------------------------------------------------------------
// Problem constants
// ---------------------------------------------------------------------------
#define N_NODES 100000
#define N_EDGES 1600000
#define D_NODE  128
#define D_EDGE  128
#define D_IN    256
#define HID     256
#define D_OUT   128

// ---------------------------------------------------------------------------
// Scratch (device globals; allocations are forbidden)
// ---------------------------------------------------------------------------
__device__ __align__(16) float g_sum[(size_t)N_NODES * D_EDGE];
__device__ int g_cnt[N_NODES];

// Weight blob in EXACT mma.sync A-fragment order, single fp16 term:
//   b32 index = layerBase + (kstep*NFT + ft)*128 + lane*4 + reg
#define WF_L2_B32 32768
#define WF_L3_B32 65536
#define WF_TOTAL_B32 81920
__device__ __align__(16) uint4 g_wfrag[WF_TOTAL_B32 / 4];

// ---------------------------------------------------------------------------
// SMEM map (MLP): single fp16 activation buffer [256 feat][72 f16], 144 B row.
// L3 f32 transpose scratch (128 x 68 f32, stride 272 B) overlays it.
// ---------------------------------------------------------------------------
#define ACT_OFF 0
#define SMEM_BYTES 36864

// ---------------------------------------------------------------------------
// PTX helpers (arch-portable, valid at compute_103)
// ---------------------------------------------------------------------------
__device__ __forceinline__ uint32_t smem_to_u32(const void* p) {
    uint32_t a;
    asm("{ .reg .u64 t; cvta.to.shared.u64 t, %1; cvt.u32.u64 %0, t; }"
        : "=r"(a) : "l"(p));
    return a;
}

#define LDMX4T(r, addr) \
    asm volatile("ldmatrix.sync.aligned.m8n8.x4.trans.shared.b16 {%0,%1,%2,%3}, [%4];" \
        : "=r"((r)[0]), "=r"((r)[1]), "=r"((r)[2]), "=r"((r)[3]) : "r"(addr))

#define MMA_F16(d, a, b0v, b1v) \
    asm volatile("mma.sync.aligned.m16n8k16.row.col.f32.f16.f16.f32 " \
        "{%0,%1,%2,%3},{%4,%5,%6,%7},{%8,%9},{%0,%1,%2,%3};" \
        : "+f"((d)[0]), "+f"((d)[1]), "+f"((d)[2]), "+f"((d)[3]) \
        : "r"((a)[0]), "r"((a)[1]), "r"((a)[2]), "r"((a)[3]), \
          "r"(b0v), "r"(b1v))

// fp32 pair -> packed f16x2 (a in low half, b in high half)
__device__ __forceinline__ uint32_t pack_f16x2(float a, float b) {
    uint32_t r;
    asm("cvt.rn.f16x2.f32 %0, %1, %2;" : "=r"(r) : "f"(b), "f"(a));
    return r;
}

// ---------------------------------------------------------------------------
// Kernel 1: zero scratch (float4 stores)
// ---------------------------------------------------------------------------
__global__ void zero_kernel() {
    int i = blockIdx.x * blockDim.x + threadIdx.x;
    const int total4 = N_NODES * D_EDGE / 4;
    if (i < total4)
        ((float4*)g_sum)[i] = make_float4(0.f, 0.f, 0.f, 0.f);
    if (i < N_NODES) g_cnt[i] = 0;
}

// ---------------------------------------------------------------------------
// Kernel 2: weight prep — single fp16 term, mma A-fragment order
// ---------------------------------------------------------------------------
__global__ void prep_kernel(const float* __restrict__ W1,
                            const float* __restrict__ W2,
                            const float* __restrict__ W3) {
    int i = blockIdx.x * blockDim.x + threadIdx.x;
    if (i >= WF_TOTAL_B32) return;
    uint32_t* blob = (uint32_t*)g_wfrag;
    const float* W; int idx, Nl, NFT;
    if (i < WF_L2_B32)      { W = W1; idx = i;             Nl = 256; NFT = 16; }
    else if (i < WF_L3_B32) { W = W2; idx = i - WF_L2_B32; Nl = 256; NFT = 16; }
    else                    { W = W3; idx = i - WF_L3_B32; Nl = 128; NFT = 8;  }
    int reg   = idx & 3;
    int lane  = (idx >> 2) & 31;
    int ft    = (idx >> 7) % NFT;
    int kstep = (idx >> 7) / NFT;
    int r = lane >> 2, t = lane & 3;
    int m = ft * 16 + r + (reg & 1) * 8;
    int k = kstep * 16 + t * 2 + (reg >> 1) * 8;
    float w0 = __ldg(W + (size_t)k * Nl + m);
    float w1 = __ldg(W + (size_t)(k + 1) * Nl + m);
    blob[i] = pack_f16x2(w0, w1);
}

// ---------------------------------------------------------------------------
// Kernel 3a: bulk scatter. CTA = 64 edges, 8 warps (8 edges/warp).
// Warp stages 8 edge rows (4 KB) in smem, then 8 lanes each issue ONE
// cp.reduce.async.bulk (512 B, 128 f32 adds offloaded to LTS).
// ---------------------------------------------------------------------------
#define EPB 64          // edges per block
__global__ void __launch_bounds__(256)
scatter_bulk_kernel(const int* __restrict__ col,
                    const float4* __restrict__ edge_attr) {
    extern __shared__ __align__(512) char sbuf[];   // 32 KB: 64 x 512 B rows
    const int tid  = threadIdx.x;
    const int warp = tid >> 5;
    const int lane = tid & 31;
    const int e0   = blockIdx.x * EPB + warp * 8;   // warp's first edge

    const float4* src = edge_attr + (size_t)e0 * 32;
    float4* dst = (float4*)(sbuf + warp * 4096);
    #pragma unroll
    for (int i = 0; i < 8; i++)
        dst[i * 32 + lane] = __ldg(src + i * 32 + lane);
    __syncwarp();
    asm volatile("fence.proxy.async.shared::cta;" ::: "memory");

    if (lane < 8) {
        int e = e0 + lane;
        int d = __ldg(col + e);
        atomicAdd(&g_cnt[d], 1);
        uint32_t saddr = smem_to_u32(sbuf + warp * 4096 + lane * 512);
        asm volatile(
            "cp.reduce.async.bulk.global.shared::cta.bulk_group.add.f32 "
            "[%0], [%1], 512;"
            :: "l"(g_sum + (size_t)d * D_EDGE), "r"(saddr) : "memory");
        asm volatile("cp.async.bulk.commit_group;" ::: "memory");
        asm volatile("cp.async.bulk.wait_group 0;" ::: "memory");
    }
}

// ---------------------------------------------------------------------------
// Kernel 3b: tail scatter (red.v4) for edges not covered by full batches.
// ---------------------------------------------------------------------------
__global__ void __launch_bounds__(256)
scatter_tail_kernel(const int* __restrict__ col,
                    const float4* __restrict__ edge_attr,
                    int start, int n_edges) {
    long long gid = (long long)blockIdx.x * blockDim.x + threadIdx.x;
    int cnt = n_edges - start;
    if (gid >= (long long)cnt * 32) return;
    int e = start + (int)(gid >> 5);
    int c = (int)(gid & 31);
    int dst = __ldg(col + e);
    if (c == 0) atomicAdd(&g_cnt[dst], 1);
    float4 v = __ldg(edge_attr + (size_t)e * 32 + c);
    float* p = g_sum + (size_t)dst * D_EDGE + c * 4;
    asm volatile("red.global.add.v4.f32 [%0], {%1,%2,%3,%4};"
                 :: "l"(p), "f"(v.x), "f"(v.y), "f"(v.z), "f"(v.w)
                 : "memory");
}

// ---------------------------------------------------------------------------
// Layer MMA: warp = NT*16 feats x 64 nodes. Single fp16 weights + acts.
// ---------------------------------------------------------------------------
template<int NT>
__device__ __forceinline__ void layer_mma(
    float acc[2][8][4],
    const uint4* __restrict__ wf,
    int ftBase, int NFT,
    uint32_t act, int lane)
{
    const uint32_t bK  = (uint32_t)(lane & 15);
    const uint32_t bMH = (uint32_t)((lane >> 4) * 8);
    #pragma unroll
    for (int kstep = 0; kstep < 16; kstep++) {
        uint32_t ah[NT][4];
        #pragma unroll
        for (int i = 0; i < NT; i++) {
            const uint4* p = wf + (size_t)(kstep * NFT + ftBase + i) * 32 + lane;
            uint4 h = __ldg(p);
            ah[i][0] = h.x; ah[i][1] = h.y; ah[i][2] = h.z; ah[i][3] = h.w;
        }
        const uint32_t kByte = (uint32_t)(kstep * 16 + (int)bK) * 144u;
        #pragma unroll
        for (int mt = 0; mt < 4; mt++) {
            const uint32_t mByte = (uint32_t)(mt * 16 + (int)bMH) * 2u;
            uint32_t bh[4];
            LDMX4T(bh, act + kByte + mByte);
            #pragma unroll
            for (int i = 0; i < NT; i++) {
                #pragma unroll
                for (int h = 0; h < 2; h++) {
                    MMA_F16(acc[i][mt * 2 + h], ah[i], bh[2 * h], bh[2 * h + 1]);
                }
            }
        }
    }
}

// ---------------------------------------------------------------------------
// Kernel 4: fused 3-layer MLP. CTA = 64 nodes, 256 threads, 2 CTAs/SM.
// ---------------------------------------------------------------------------
__global__ void __launch_bounds__(256, 2)
mlp_kernel(const float* __restrict__ x,
           const float* __restrict__ b1,
           const float* __restrict__ b2,
           const float* __restrict__ b3,
           float* __restrict__ out, int n)
{
    extern __shared__ char sm[];
    const uint32_t sb  = smem_to_u32(sm);
    const uint32_t act = sb + ACT_OFF;

    const int tid  = threadIdx.x;
    const int warp = tid >> 5;
    const int lane = tid & 31;
    const int g    = lane >> 2;
    const int t    = lane & 3;
    const int m0   = blockIdx.x * 64;

    // ---- input fill: thread = (feat-group q of 16, node-quad p) ------------
    // 16 LDG.128 + 16 STS.64 per thread (vs 64 STS.16 before; <=2-way bank
    // conflict since warp = 2 q-groups x 16 quads -> bank = 2p + const).
    {
        int q = tid >> 4;           // feature group 0..15 (16 feats each)
        int p = tid & 15;           // node quad: nodes 4p..4p+3
        float inv[4];
        const float* base[4];
        bool valid[4];
        #pragma unroll
        for (int j = 0; j < 4; j++) {
            int m = m0 + 4 * p + j;
            valid[j] = (m < n);
            int mm = valid[j] ? m : 0;
            if (q < 8) {
                base[j] = x + (size_t)mm * D_NODE;
                inv[j] = 1.0f;
            } else {
                base[j] = g_sum + (size_t)mm * D_EDGE;
                inv[j] = valid[j]
                       ? 1.0f / fmaxf((float)__ldg(&g_cnt[mm]), 1.0f) : 1.0f;
            }
        }
        int fbase = (q < 8) ? q * 16 : (q - 8) * 16;   // within x / g_sum row
        #pragma unroll
        for (int c = 0; c < 4; c++) {                  // 4 float4 chunks
            float4 v[4];
            #pragma unroll
            for (int j = 0; j < 4; j++) {
                v[j] = make_float4(0.f, 0.f, 0.f, 0.f);
                if (valid[j]) {
                    v[j] = __ldg((const float4*)base[j] + (fbase >> 2) + c);
                    v[j].x *= inv[j]; v[j].y *= inv[j];
                    v[j].z *= inv[j]; v[j].w *= inv[j];
                }
            }
            const float* vf[4] = {&v[0].x, &v[1].x, &v[2].x, &v[3].x};
            #pragma unroll
            for (int e = 0; e < 4; e++) {              // 4 feats per chunk
                int f = q * 16 + c * 4 + e;            // act row
                uint2 pk;
                pk.x = pack_f16x2(vf[0][e], vf[1][e]); // nodes 4p, 4p+1
                pk.y = pack_f16x2(vf[2][e], vf[3][e]); // nodes 4p+2, 4p+3
                *(uint2*)(sm + ACT_OFF + (size_t)f * 144 + (size_t)p * 8) = pk;
            }
        }
    }
    __syncthreads();

    float acc[2][8][4];

    // ---- Layers 1 & 2 (K=256, N=256) ---------------------------------------
    #pragma unroll 1
    for (int L = 0; L < 2; L++) {
        const uint4* wf = g_wfrag + (L == 0 ? 0 : WF_L2_B32 / 4);
        #pragma unroll
        for (int i = 0; i < 2; i++)
            #pragma unroll
            for (int mt = 0; mt < 8; mt++)
                #pragma unroll
                for (int q = 0; q < 4; q++) acc[i][mt][q] = 0.f;

        layer_mma<2>(acc, wf, warp * 2, 16, act, lane);

        __syncthreads();     // all warps done READING act for this layer

        const float* bias = (L == 0) ? b1 : b2;
        const int nb = warp * 32;
        #pragma unroll
        for (int i = 0; i < 2; i++) {
            int fb = nb + i * 16;
            float bg  = __ldg(bias + fb + g);
            float bg8 = __ldg(bias + fb + g + 8);
            size_t rowG  = (size_t)(fb + g) * 144;
            size_t rowG8 = (size_t)(fb + g + 8) * 144;
            #pragma unroll
            for (int mt = 0; mt < 8; mt++) {
                float v0 = fmaxf(acc[i][mt][0] + bg,  0.f);
                float v1 = fmaxf(acc[i][mt][1] + bg,  0.f);
                float v2 = fmaxf(acc[i][mt][2] + bg8, 0.f);
                float v3 = fmaxf(acc[i][mt][3] + bg8, 0.f);
                uint32_t h01 = pack_f16x2(v0, v1);
                uint32_t h23 = pack_f16x2(v2, v3);
                size_t mB = (size_t)(mt * 8 + 2 * t) * 2;
                *(uint32_t*)(sm + ACT_OFF + rowG  + mB) = h01;
                *(uint32_t*)(sm + ACT_OFF + rowG8 + mB) = h23;
            }
        }
        __syncthreads();     // writes visible before next layer reads
    }

    // ---- Layer 3 (K=256, N=128) ---------------------------------------------
    #pragma unroll
    for (int mt = 0; mt < 8; mt++)
        #pragma unroll
        for (int q = 0; q < 4; q++) acc[0][mt][q] = 0.f;

    layer_mma<1>(acc, g_wfrag + WF_L3_B32 / 4, warp, 8, act, lane);

    // ---- final epilogue: bias, transpose via f32 scratch, coalesced store ---
    {
        const int nb = warp * 16;
        float bg  = __ldg(b3 + nb + g);
        float bg8 = __ldg(b3 + nb + g + 8);
        __syncthreads();     // all done reading act (scratch overlays it)
        #pragma unroll
        for (int mt = 0; mt < 8; mt++) {
            float2 v01 = make_float2(acc[0][mt][0] + bg,  acc[0][mt][1] + bg);
            float2 v23 = make_float2(acc[0][mt][2] + bg8, acc[0][mt][3] + bg8);
            size_t mB = (size_t)(mt * 8 + 2 * t) * 4;
            *(float2*)(sm + (size_t)(nb + g)     * 272 + mB) = v01;
            *(float2*)(sm + (size_t)(nb + g + 8) * 272 + mB) = v23;
        }
        __syncthreads();
        int mloc = tid >> 2, fgrp = tid & 3;
        int m = m0 + mloc;
        if (m < n) {
            const float* scr = (const float*)sm;
            #pragma unroll
            for (int i = 0; i < 8; i++) {
                int f = fgrp * 32 + i * 4;
                float4 v;
                v.x = scr[(f + 0) * 68 + mloc];
                v.y = scr[(f + 1) * 68 + mloc];
                v.z = scr[(f + 2) * 68 + mloc];
                v.w = scr[(f + 3) * 68 + mloc];
                *(float4*)(out + (size_t)m * D_OUT + f) = v;
            }
        }
    }
}

// ---------------------------------------------------------------------------
// kernel_launch
// Inputs: 0=x [N,128] f32, 1=edge_index [2,E] i32, 2=edge_attr [E,128] f32,
//         3=W1 [256,256], 4=b1, 5=W2 [256,256], 6=b2, 7=W3 [256,128], 8=b3.
// ---------------------------------------------------------------------------
extern "C" void kernel_launch(void* const* d_in, const int* in_sizes, int n_in,
                              void* d_out, int out_size) {
    const float* x  = (const float*)d_in[0];
    const int* ei   = (const int*)d_in[1];
    const float* ea = (const float*)d_in[2];
    const float* W1 = (const float*)d_in[3];
    const float* b1 = (const float*)d_in[4];
    const float* W2 = (const float*)d_in[5];
    const float* b2 = (const float*)d_in[6];
    const float* W3 = (const float*)d_in[7];
    const float* b3 = (const float*)d_in[8];
    float* out = (float*)d_out;

    const int n = in_sizes[0] / D_NODE;              // 100000
    const int n_edges = in_sizes[2] / D_EDGE;        // 1600000
    const int* col = ei + n_edges;                   // edge_index[1]

    // Lazy one-time setup (first call is the uncaptured correctness run)
    static int inited = 0;
    static cudaStream_t s2;
    static cudaEvent_t evFork, evJoin;
    if (!inited) {
        cudaStreamCreateWithFlags(&s2, cudaStreamNonBlocking);
        cudaEventCreateWithFlags(&evFork, cudaEventDisableTiming);
        cudaEventCreateWithFlags(&evJoin, cudaEventDisableTiming);
        cudaFuncSetAttribute(mlp_kernel,
                             cudaFuncAttributeMaxDynamicSharedMemorySize,
                             SMEM_BYTES);
        inited = 1;
    }

    // Fork: prep (feeds only the MLP) runs concurrent with zero+scatter.
    cudaEventRecord(evFork, 0);
    cudaStreamWaitEvent(s2, evFork, 0);
    prep_kernel<<<(WF_TOTAL_B32 + 255) / 256, 256, 0, s2>>>(W1, W2, W3);
    cudaEventRecord(evJoin, s2);

    // Main chain: zero -> scatter
    {
        int total4 = N_NODES * D_EDGE / 4;
        zero_kernel<<<(total4 + 255) / 256, 256>>>();
    }
    {
        int full = n_edges / EPB;
        if (full > 0)
            scatter_bulk_kernel<<<full, 256, EPB * 512>>>(col, (const float4*)ea);
        int start = full * EPB;
        if (start < n_edges) {
            long long threads = (long long)(n_edges - start) * 32;
            int blocks = (int)((threads + 255) / 256);
            scatter_tail_kernel<<<blocks, 256>>>(col, (const float4*)ea,
                                                 start, n_edges);
        }
    }

    // Join: MLP needs both scatter (main chain) and prep (s2)
    cudaStreamWaitEvent(0, evJoin, 0);
    {
        int blocks = (n + 63) / 64;                  // 1563
        mlp_kernel<<<blocks, 256, SMEM_BYTES>>>(x, b1, b2, b3, out, n);
    }
}